// round 9
// baseline (speedup 1.0000x reference)
#include <cuda_runtime.h>
#include <cuda_fp16.h>

#define NU 100000
#define NI 100000
#define DD 64
#define NL 3
#define NE 6400000
#define NB 16384
#define NN (NU + NI)

#define SCAN_BS 512
#define SCAN_NBLK ((NN + SCAN_BS - 1) / SCAN_BS)   // 391

// Scratch — __device__ globals, no allocation.
__device__ __half g_embs[NL + 1][(size_t)NN * DD];  // fp16 per-layer outputs
__device__ int    g_count[NN];       // row degrees; drained to 0 by k_place
__device__ int    g_rowptr[NN + 1];  // CSR offsets
__device__ int2   g_edges[NE];       // packed {col, val-bits}
// scan coordination (reset by k_dot each call; zero-init at load)
__device__ int    g_blk_agg[SCAN_NBLK];
__device__ int    g_blk_off[SCAN_NBLK];
__device__ int    g_arrcount;
__device__ int    g_release;

__device__ __forceinline__ float sigmoidf(float x) {
    return 1.0f / (1.0f + __expf(-x));
}
__device__ __forceinline__ unsigned int h2_to_u(__half2 h) {
    return *reinterpret_cast<unsigned int*>(&h);
}
__device__ __forceinline__ __half2 u_to_h2(unsigned int u) {
    return *reinterpret_cast<__half2*>(&u);
}

// ---------------------------------------------------------------------------
// Fused layer-0 + row histogram. idx < NE: count edge rows. idx < n4: fuse0.
// g_count starts at 0: zero-init at load, drained to 0 by k_place each call.
// ---------------------------------------------------------------------------
__global__ void k_fuse0count(const float* __restrict__ ue, const float* __restrict__ ie,
                             const float* __restrict__ se, const float* __restrict__ he,
                             const float* __restrict__ ulw, const float* __restrict__ ilw,
                             const int* __restrict__ er) {
    int idx = blockIdx.x * blockDim.x + threadIdx.x;
    if (idx < NE) atomicAdd(&g_count[__ldcs(&er[idx])], 1);
    const int n4 = NN * DD / 4;
    if (idx >= n4) return;
    float4 r;
    if (idx < NU * DD / 4) {
        float a = sigmoidf(ulw[0]);
        float4 x = ((const float4*)ue)[idx];
        float4 s = ((const float4*)se)[idx];
        r.x = a * x.x + (1.0f - a) * s.x;
        r.y = a * x.y + (1.0f - a) * s.y;
        r.z = a * x.z + (1.0f - a) * s.z;
        r.w = a * x.w + (1.0f - a) * s.w;
    } else {
        int j = idx - NU * DD / 4;
        float b = sigmoidf(ilw[0]);
        float4 x = ((const float4*)ie)[j];
        float4 h = ((const float4*)he)[j];
        r.x = b * x.x + (1.0f - b) * h.x;
        r.y = b * x.y + (1.0f - b) * h.y;
        r.z = b * x.z + (1.0f - b) * h.z;
        r.w = b * x.w + (1.0f - b) * h.w;
    }
    uint2 hp;
    hp.x = h2_to_u(__floats2half2_rn(r.x, r.y));
    hp.y = h2_to_u(__floats2half2_rn(r.z, r.w));
    ((uint2*)g_embs[0])[idx] = hp;
}

// ---------------------------------------------------------------------------
// Single-kernel exclusive scan of g_count -> g_rowptr.
// Block-local scan; last-arriving block scans the 391 aggregates, releases all.
// All SCAN_NBLK blocks are co-resident (391 < 148*4) => spin is safe.
// ---------------------------------------------------------------------------
__device__ __forceinline__ int block_incl_scan(int v, int tid, int* warp_sums) {
    int lane = tid & 31, wid = tid >> 5;
    int x = v;
    #pragma unroll
    for (int o = 1; o < 32; o <<= 1) {
        int y = __shfl_up_sync(0xffffffffu, x, o);
        if (lane >= o) x += y;
    }
    if (lane == 31) warp_sums[wid] = x;
    __syncthreads();
    if (wid == 0) {
        int s = (lane < SCAN_BS / 32) ? warp_sums[lane] : 0;
        #pragma unroll
        for (int o = 1; o < SCAN_BS / 32; o <<= 1) {
            int y = __shfl_up_sync(0xffffffffu, s, o);
            if (lane >= o) s += y;
        }
        if (lane < SCAN_BS / 32) warp_sums[lane] = s;
    }
    __syncthreads();
    return x + (wid ? warp_sums[wid - 1] : 0);
}

__global__ void k_scan() {
    __shared__ int warp_sums[SCAN_BS / 32];
    __shared__ int s_last;
    int b = blockIdx.x, tid = threadIdx.x;
    int i = b * SCAN_BS + tid;
    int v = (i < NN) ? g_count[i] : 0;
    int incl = block_incl_scan(v, tid, warp_sums);
    int total = warp_sums[SCAN_BS / 32 - 1];

    if (tid == 0) {
        g_blk_agg[b] = total;
        __threadfence();
        int t = atomicAdd(&g_arrcount, 1);
        s_last = (t == SCAN_NBLK - 1);
    }
    __syncthreads();

    if (s_last) {
        // this block scans the aggregates (SCAN_NBLK <= SCAN_BS)
        int av = (tid < SCAN_NBLK) ? g_blk_agg[tid] : 0;
        __syncthreads();  // warp_sums reuse
        int aincl = block_incl_scan(av, tid, warp_sums);
        if (tid < SCAN_NBLK) g_blk_off[tid] = aincl - av;   // exclusive
        __threadfence();
        __syncthreads();
        if (tid == 0) atomicExch(&g_release, 1);
    }
    if (tid == 0) {
        while (atomicAdd(&g_release, 0) == 0) { }
    }
    __syncthreads();

    int off = g_blk_off[b];
    if (i < NN) g_rowptr[i] = incl - v + off;   // exclusive global
    if (b == 0 && tid == 0) g_rowptr[NN] = NE;
}

// ---------------------------------------------------------------------------
// Place packed {col,val}: position via draining g_count (no g_woff needed).
// Leaves g_count == 0 for the next call.
// ---------------------------------------------------------------------------
__global__ void k_place(const float* __restrict__ ev, const int* __restrict__ er,
                        const int* __restrict__ ec) {
    int e = blockIdx.x * blockDim.x + threadIdx.x;
    if (e >= NE) return;
    int row = __ldcs(&er[e]);
    int old = atomicAdd(&g_count[row], -1);       // old in [deg..1]
    int pos = __ldg(&g_rowptr[row]) + old - 1;
    int2 rec = make_int2(__ldcs(&ec[e]), __float_as_int(__ldcs(&ev[e])));
    __stcg(&g_edges[pos], rec);
}

// ---------------------------------------------------------------------------
// Gather SpMM (fp16 table, fp32 accumulate) + per-layer fusion.
// 8 threads per row; each handles 8 consecutive dims (one 16B load per edge).
// ---------------------------------------------------------------------------
__global__ void k_spmm_fuse(const float* __restrict__ se, const float* __restrict__ he,
                            const float* __restrict__ ulw, const float* __restrict__ ilw,
                            int layer) {
    int tid = blockIdx.x * blockDim.x + threadIdx.x;
    int row = tid >> 3;
    int c   = tid & 7;
    if (row >= NN) return;

    const uint4* cur  = (const uint4*)g_embs[layer - 1];
    uint4*       next = (uint4*)g_embs[layer];

    int s = __ldg(&g_rowptr[row]);
    int t = __ldg(&g_rowptr[row + 1]);

    float2 s0 = make_float2(0.f, 0.f), s1 = s0, s2 = s0, s3 = s0;

    int e = s;
    for (; e + 4 <= t; e += 4) {
        int2 e0 = __ldcs(&g_edges[e + 0]);
        int2 e1 = __ldcs(&g_edges[e + 1]);
        int2 e2 = __ldcs(&g_edges[e + 2]);
        int2 e3 = __ldcs(&g_edges[e + 3]);
        uint4 x0 = __ldg(&cur[e0.x * 8 + c]);
        uint4 x1 = __ldg(&cur[e1.x * 8 + c]);
        uint4 x2 = __ldg(&cur[e2.x * 8 + c]);
        uint4 x3 = __ldg(&cur[e3.x * 8 + c]);
        float v0 = __int_as_float(e0.y), v1 = __int_as_float(e1.y);
        float v2 = __int_as_float(e2.y), v3 = __int_as_float(e3.y);
        float2 f;
        f = __half22float2(u_to_h2(x0.x)); s0.x += v0*f.x; s0.y += v0*f.y;
        f = __half22float2(u_to_h2(x0.y)); s1.x += v0*f.x; s1.y += v0*f.y;
        f = __half22float2(u_to_h2(x0.z)); s2.x += v0*f.x; s2.y += v0*f.y;
        f = __half22float2(u_to_h2(x0.w)); s3.x += v0*f.x; s3.y += v0*f.y;
        f = __half22float2(u_to_h2(x1.x)); s0.x += v1*f.x; s0.y += v1*f.y;
        f = __half22float2(u_to_h2(x1.y)); s1.x += v1*f.x; s1.y += v1*f.y;
        f = __half22float2(u_to_h2(x1.z)); s2.x += v1*f.x; s2.y += v1*f.y;
        f = __half22float2(u_to_h2(x1.w)); s3.x += v1*f.x; s3.y += v1*f.y;
        f = __half22float2(u_to_h2(x2.x)); s0.x += v2*f.x; s0.y += v2*f.y;
        f = __half22float2(u_to_h2(x2.y)); s1.x += v2*f.x; s1.y += v2*f.y;
        f = __half22float2(u_to_h2(x2.z)); s2.x += v2*f.x; s2.y += v2*f.y;
        f = __half22float2(u_to_h2(x2.w)); s3.x += v2*f.x; s3.y += v2*f.y;
        f = __half22float2(u_to_h2(x3.x)); s0.x += v3*f.x; s0.y += v3*f.y;
        f = __half22float2(u_to_h2(x3.y)); s1.x += v3*f.x; s1.y += v3*f.y;
        f = __half22float2(u_to_h2(x3.z)); s2.x += v3*f.x; s2.y += v3*f.y;
        f = __half22float2(u_to_h2(x3.w)); s3.x += v3*f.x; s3.y += v3*f.y;
    }
    for (; e < t; e++) {
        int2 ed = __ldcs(&g_edges[e]);
        uint4 x = __ldg(&cur[ed.x * 8 + c]);
        float v = __int_as_float(ed.y);
        float2 f;
        f = __half22float2(u_to_h2(x.x)); s0.x += v*f.x; s0.y += v*f.y;
        f = __half22float2(u_to_h2(x.y)); s1.x += v*f.x; s1.y += v*f.y;
        f = __half22float2(u_to_h2(x.z)); s2.x += v*f.x; s2.y += v*f.y;
        f = __half22float2(u_to_h2(x.w)); s3.x += v*f.x; s3.y += v*f.y;
    }

    bool isU = row < NU;
    float w = sigmoidf(isU ? ulw[layer] : ilw[layer]);
    float omw = 1.0f - w;
    const float4* sdp = isU ? (const float4*)se + (size_t)row * 16 + c * 2
                            : (const float4*)he + (size_t)(row - NU) * 16 + c * 2;
    float4 sa = __ldg(sdp);
    float4 sb = __ldg(sdp + 1);

    uint4 hout;
    hout.x = h2_to_u(__floats2half2_rn(w * s0.x + omw * sa.x, w * s0.y + omw * sa.y));
    hout.y = h2_to_u(__floats2half2_rn(w * s1.x + omw * sa.z, w * s1.y + omw * sa.w));
    hout.z = h2_to_u(__floats2half2_rn(w * s2.x + omw * sb.x, w * s2.y + omw * sb.y));
    hout.w = h2_to_u(__floats2half2_rn(w * s3.x + omw * sb.z, w * s3.y + omw * sb.w));
    next[row * 8 + c] = hout;
}

// ---------------------------------------------------------------------------
// Final dot over on-the-fly 4-layer sum; also resets scan state for next call.
// ---------------------------------------------------------------------------
__global__ void k_dot(const int* __restrict__ users, const int* __restrict__ items,
                      float* __restrict__ out) {
    int gt = blockIdx.x * blockDim.x + threadIdx.x;
    if (gt == 0) { g_arrcount = 0; g_release = 0; }
    int w = gt >> 5;
    int l = threadIdx.x & 31;
    if (w >= NB) return;
    size_t uo = (size_t)users[w] * 32 + l;
    size_t io = (size_t)(NU + items[w]) * 32 + l;
    float ux = 0.f, uy = 0.f, ix = 0.f, iy = 0.f;
    #pragma unroll
    for (int L = 0; L <= NL; L++) {
        float2 fu = __half22float2(((const __half2*)g_embs[L])[uo]);
        float2 fi = __half22float2(((const __half2*)g_embs[L])[io]);
        ux += fu.x; uy += fu.y;
        ix += fi.x; iy += fi.y;
    }
    float s = ux * ix + uy * iy;
    #pragma unroll
    for (int o = 16; o > 0; o >>= 1)
        s += __shfl_down_sync(0xffffffffu, s, o);
    if (l == 0) out[w] = s * (1.0f / 16.0f);
}

extern "C" void kernel_launch(void* const* d_in, const int* in_sizes, int n_in,
                              void* d_out, int out_size) {
    const float* user_emb    = (const float*)d_in[0];
    const float* item_emb    = (const float*)d_in[1];
    const float* symptom_emb = (const float*)d_in[2];
    const float* herb_emb    = (const float*)d_in[3];
    const float* user_lw     = (const float*)d_in[4];
    const float* item_lw     = (const float*)d_in[5];
    const float* edge_val    = (const float*)d_in[6];
    const int*   edge_row    = (const int*)d_in[7];
    const int*   edge_col    = (const int*)d_in[8];
    const int*   users       = (const int*)d_in[9];
    const int*   items       = (const int*)d_in[10];
    float* out = (float*)d_out;

    const int TB = 256;
    const int gEdge = (NE + TB - 1) / TB;
    const int gRow  = (NN * 8 + TB - 1) / TB;

    k_fuse0count<<<gEdge, TB>>>(user_emb, item_emb, symptom_emb, herb_emb,
                                user_lw, item_lw, edge_row);
    k_scan<<<SCAN_NBLK, SCAN_BS>>>();
    k_place<<<gEdge, TB>>>(edge_val, edge_row, edge_col);

    for (int layer = 1; layer <= NL; layer++) {
        k_spmm_fuse<<<gRow, TB>>>(symptom_emb, herb_emb, user_lw, item_lw, layer);
    }
    k_dot<<<(NB * 32 + TB - 1) / TB, TB>>>(users, items, out);
}

// round 10
// speedup vs baseline: 1.0290x; 1.0290x over previous
#include <cuda_runtime.h>
#include <cuda_fp16.h>

#define NU 100000
#define NI 100000
#define DD 64
#define NL 3
#define NE 6400000
#define NB 16384
#define NN (NU + NI)

#define SCAN_BS 512
#define SCAN_NBLK ((NN + SCAN_BS - 1) / SCAN_BS)   // 391

// Scratch — __device__ globals, no allocation.
__device__ __half g_embs[NL + 1][(size_t)NN * DD];  // fp16 per-layer outputs
__device__ int    g_count[NN];
__device__ int    g_rowptr[NN + 1];
__device__ int    g_woff[NN];
__device__ int    g_bsum[SCAN_NBLK];
__device__ __align__(16) int2 g_edges[NE];          // packed {col, val-bits}

__device__ __forceinline__ float sigmoidf(float x) {
    return 1.0f / (1.0f + __expf(-x));
}
__device__ __forceinline__ unsigned int h2_to_u(__half2 h) {
    return *reinterpret_cast<unsigned int*>(&h);
}
__device__ __forceinline__ __half2 u_to_h2(unsigned int u) {
    return *reinterpret_cast<__half2*>(&u);
}

// ---------------------------------------------------------------------------
// Layer-0 fusion + zero row counters. g_embs[0](fp16) = fused layer-0.
// ---------------------------------------------------------------------------
__global__ void k_fuse0(const float* __restrict__ ue, const float* __restrict__ ie,
                        const float* __restrict__ se, const float* __restrict__ he,
                        const float* __restrict__ ulw, const float* __restrict__ ilw) {
    int idx = blockIdx.x * blockDim.x + threadIdx.x;
    if (idx < NN) g_count[idx] = 0;
    const int n4 = NN * DD / 4;
    if (idx >= n4) return;
    float4 r;
    if (idx < NU * DD / 4) {
        float a = sigmoidf(ulw[0]);
        float4 x = ((const float4*)ue)[idx];
        float4 s = ((const float4*)se)[idx];
        r.x = a * x.x + (1.0f - a) * s.x;
        r.y = a * x.y + (1.0f - a) * s.y;
        r.z = a * x.z + (1.0f - a) * s.z;
        r.w = a * x.w + (1.0f - a) * s.w;
    } else {
        int j = idx - NU * DD / 4;
        float b = sigmoidf(ilw[0]);
        float4 x = ((const float4*)ie)[j];
        float4 h = ((const float4*)he)[j];
        r.x = b * x.x + (1.0f - b) * h.x;
        r.y = b * x.y + (1.0f - b) * h.y;
        r.z = b * x.z + (1.0f - b) * h.z;
        r.w = b * x.w + (1.0f - b) * h.w;
    }
    uint2 hp;
    hp.x = h2_to_u(__floats2half2_rn(r.x, r.y));
    hp.y = h2_to_u(__floats2half2_rn(r.z, r.w));
    ((uint2*)g_embs[0])[idx] = hp;
}

// ---------------------------------------------------------------------------
// CSR build (R6-proven pipeline)
// ---------------------------------------------------------------------------
__global__ void k_count(const int* __restrict__ er) {
    int e = blockIdx.x * blockDim.x + threadIdx.x;
    if (e >= NE) return;
    atomicAdd(&g_count[er[e]], 1);
}

__global__ void k_scan_blocks() {
    __shared__ int sh[SCAN_BS];
    int i = blockIdx.x * SCAN_BS + threadIdx.x;
    int v = (i < NN) ? g_count[i] : 0;
    sh[threadIdx.x] = v;
    __syncthreads();
    #pragma unroll
    for (int o = 1; o < SCAN_BS; o <<= 1) {
        int t = (threadIdx.x >= o) ? sh[threadIdx.x - o] : 0;
        __syncthreads();
        sh[threadIdx.x] += t;
        __syncthreads();
    }
    if (i < NN) g_rowptr[i] = sh[threadIdx.x] - v;
    if (threadIdx.x == SCAN_BS - 1) g_bsum[blockIdx.x] = sh[SCAN_BS - 1];
}

__global__ void k_scan_tops() {
    __shared__ int sh[SCAN_BS];
    int v = (threadIdx.x < SCAN_NBLK) ? g_bsum[threadIdx.x] : 0;
    sh[threadIdx.x] = v;
    __syncthreads();
    #pragma unroll
    for (int o = 1; o < SCAN_BS; o <<= 1) {
        int t = (threadIdx.x >= o) ? sh[threadIdx.x - o] : 0;
        __syncthreads();
        sh[threadIdx.x] += t;
        __syncthreads();
    }
    if (threadIdx.x < SCAN_NBLK) g_bsum[threadIdx.x] = sh[threadIdx.x] - v;
}

__global__ void k_scan_add() {
    int i = blockIdx.x * blockDim.x + threadIdx.x;
    if (i >= NN) return;
    int p = g_rowptr[i] + g_bsum[i / SCAN_BS];
    g_rowptr[i] = p;
    g_woff[i] = p;
    if (i == 0) g_rowptr[NN] = NE;
}

__global__ void k_place(const float* __restrict__ ev, const int* __restrict__ er,
                        const int* __restrict__ ec) {
    int e = blockIdx.x * blockDim.x + threadIdx.x;
    if (e >= NE) return;
    int row = er[e];
    int pos = atomicAdd(&g_woff[row], 1);
    g_edges[pos] = make_int2(ec[e], __float_as_int(ev[e]));
}

// ---------------------------------------------------------------------------
// Gather SpMM (fp16 table, fp32 accumulate) + per-layer fusion.
// 8 threads per row, 8 consecutive dims each. Edge records loaded as uint4
// pairs (2 edges per LDG.128), 8-edge unroll for MLP.
// ---------------------------------------------------------------------------
__device__ __forceinline__ void acc_edge(float2& s0, float2& s1, float2& s2, float2& s3,
                                         float v, uint4 x) {
    float2 f;
    f = __half22float2(u_to_h2(x.x)); s0.x += v * f.x; s0.y += v * f.y;
    f = __half22float2(u_to_h2(x.y)); s1.x += v * f.x; s1.y += v * f.y;
    f = __half22float2(u_to_h2(x.z)); s2.x += v * f.x; s2.y += v * f.y;
    f = __half22float2(u_to_h2(x.w)); s3.x += v * f.x; s3.y += v * f.y;
}

__global__ void k_spmm_fuse(const float* __restrict__ se, const float* __restrict__ he,
                            const float* __restrict__ ulw, const float* __restrict__ ilw,
                            int layer) {
    int tid = blockIdx.x * blockDim.x + threadIdx.x;
    int row = tid >> 3;
    int c   = tid & 7;
    if (row >= NN) return;

    const uint4* cur  = (const uint4*)g_embs[layer - 1];
    uint4*       next = (uint4*)g_embs[layer];

    int s = __ldg(&g_rowptr[row]);
    int t = __ldg(&g_rowptr[row + 1]);

    float2 s0 = make_float2(0.f, 0.f), s1 = s0, s2 = s0, s3 = s0;

    int e = s;
    // peel to 16B alignment of g_edges pair reads
    if (e < t && (e & 1)) {
        int2 ed = __ldg(&g_edges[e]);
        uint4 x = __ldg(&cur[ed.x * 8 + c]);
        acc_edge(s0, s1, s2, s3, __int_as_float(ed.y), x);
        e++;
    }
    // 8 edges per iteration: 4 LDG.128 edge loads + 8 LDG.128 gathers
    for (; e + 8 <= t; e += 8) {
        uint4 p0 = __ldg((const uint4*)&g_edges[e + 0]);
        uint4 p1 = __ldg((const uint4*)&g_edges[e + 2]);
        uint4 p2 = __ldg((const uint4*)&g_edges[e + 4]);
        uint4 p3 = __ldg((const uint4*)&g_edges[e + 6]);
        uint4 xa0 = __ldg(&cur[(int)p0.x * 8 + c]);
        uint4 xb0 = __ldg(&cur[(int)p0.z * 8 + c]);
        uint4 xa1 = __ldg(&cur[(int)p1.x * 8 + c]);
        uint4 xb1 = __ldg(&cur[(int)p1.z * 8 + c]);
        uint4 xa2 = __ldg(&cur[(int)p2.x * 8 + c]);
        uint4 xb2 = __ldg(&cur[(int)p2.z * 8 + c]);
        uint4 xa3 = __ldg(&cur[(int)p3.x * 8 + c]);
        uint4 xb3 = __ldg(&cur[(int)p3.z * 8 + c]);
        acc_edge(s0, s1, s2, s3, __int_as_float(p0.y), xa0);
        acc_edge(s0, s1, s2, s3, __int_as_float(p0.w), xb0);
        acc_edge(s0, s1, s2, s3, __int_as_float(p1.y), xa1);
        acc_edge(s0, s1, s2, s3, __int_as_float(p1.w), xb1);
        acc_edge(s0, s1, s2, s3, __int_as_float(p2.y), xa2);
        acc_edge(s0, s1, s2, s3, __int_as_float(p2.w), xb2);
        acc_edge(s0, s1, s2, s3, __int_as_float(p3.y), xa3);
        acc_edge(s0, s1, s2, s3, __int_as_float(p3.w), xb3);
    }
    // pairs
    for (; e + 2 <= t; e += 2) {
        uint4 p = __ldg((const uint4*)&g_edges[e]);
        uint4 xa = __ldg(&cur[(int)p.x * 8 + c]);
        uint4 xb = __ldg(&cur[(int)p.z * 8 + c]);
        acc_edge(s0, s1, s2, s3, __int_as_float(p.y), xa);
        acc_edge(s0, s1, s2, s3, __int_as_float(p.w), xb);
    }
    // tail
    if (e < t) {
        int2 ed = __ldg(&g_edges[e]);
        uint4 x = __ldg(&cur[ed.x * 8 + c]);
        acc_edge(s0, s1, s2, s3, __int_as_float(ed.y), x);
    }

    bool isU = row < NU;
    float w = sigmoidf(isU ? ulw[layer] : ilw[layer]);
    float omw = 1.0f - w;
    const float4* sdp = isU ? (const float4*)se + (size_t)row * 16 + c * 2
                            : (const float4*)he + (size_t)(row - NU) * 16 + c * 2;
    float4 sa = __ldg(sdp);
    float4 sb = __ldg(sdp + 1);

    uint4 hout;
    hout.x = h2_to_u(__floats2half2_rn(w * s0.x + omw * sa.x, w * s0.y + omw * sa.y));
    hout.y = h2_to_u(__floats2half2_rn(w * s1.x + omw * sa.z, w * s1.y + omw * sa.w));
    hout.z = h2_to_u(__floats2half2_rn(w * s2.x + omw * sb.x, w * s2.y + omw * sb.y));
    hout.w = h2_to_u(__floats2half2_rn(w * s3.x + omw * sb.z, w * s3.y + omw * sb.w));
    next[row * 8 + c] = hout;
}

// ---------------------------------------------------------------------------
// Final dot over on-the-fly 4-layer sum.
// ---------------------------------------------------------------------------
__global__ void k_dot(const int* __restrict__ users, const int* __restrict__ items,
                      float* __restrict__ out) {
    int w = (blockIdx.x * blockDim.x + threadIdx.x) >> 5;
    int l = threadIdx.x & 31;
    if (w >= NB) return;
    size_t uo = (size_t)users[w] * 32 + l;
    size_t io = (size_t)(NU + items[w]) * 32 + l;
    float ux = 0.f, uy = 0.f, ix = 0.f, iy = 0.f;
    #pragma unroll
    for (int L = 0; L <= NL; L++) {
        float2 fu = __half22float2(((const __half2*)g_embs[L])[uo]);
        float2 fi = __half22float2(((const __half2*)g_embs[L])[io]);
        ux += fu.x; uy += fu.y;
        ix += fi.x; iy += fi.y;
    }
    float s = ux * ix + uy * iy;
    #pragma unroll
    for (int o = 16; o > 0; o >>= 1)
        s += __shfl_down_sync(0xffffffffu, s, o);
    if (l == 0) out[w] = s * (1.0f / 16.0f);
}

extern "C" void kernel_launch(void* const* d_in, const int* in_sizes, int n_in,
                              void* d_out, int out_size) {
    const float* user_emb    = (const float*)d_in[0];
    const float* item_emb    = (const float*)d_in[1];
    const float* symptom_emb = (const float*)d_in[2];
    const float* herb_emb    = (const float*)d_in[3];
    const float* user_lw     = (const float*)d_in[4];
    const float* item_lw     = (const float*)d_in[5];
    const float* edge_val    = (const float*)d_in[6];
    const int*   edge_row    = (const int*)d_in[7];
    const int*   edge_col    = (const int*)d_in[8];
    const int*   users       = (const int*)d_in[9];
    const int*   items       = (const int*)d_in[10];
    float* out = (float*)d_out;

    const int n4 = NN * DD / 4;
    const int TB = 256;
    const int gElem = (n4 + TB - 1) / TB;
    const int gEdge = (NE + TB - 1) / TB;
    const int gRow  = (NN * 8 + TB - 1) / TB;

    k_fuse0<<<gElem, TB>>>(user_emb, item_emb, symptom_emb, herb_emb, user_lw, item_lw);
    k_count<<<gEdge, TB>>>(edge_row);
    k_scan_blocks<<<SCAN_NBLK, SCAN_BS>>>();
    k_scan_tops<<<1, SCAN_BS>>>();
    k_scan_add<<<(NN + TB - 1) / TB, TB>>>();
    k_place<<<gEdge, TB>>>(edge_val, edge_row, edge_col);

    for (int layer = 1; layer <= NL; layer++) {
        k_spmm_fuse<<<gRow, TB>>>(symptom_emb, herb_emb, user_lw, item_lw, layer);
    }
    k_dot<<<(NB * 32 + TB - 1) / TB, TB>>>(users, items, out);
}

// round 11
// speedup vs baseline: 1.0798x; 1.0494x over previous
#include <cuda_runtime.h>
#include <cuda_fp16.h>

#define NU 100000
#define NI 100000
#define DD 64
#define NL 3
#define NE 6400000
#define NB 16384
#define NN (NU + NI)

#define SCAN_BS 512
#define SCAN_NBLK ((NN + SCAN_BS - 1) / SCAN_BS)   // 391

// Scratch — __device__ globals, no allocation.
__device__ __half g_embs[NL + 1][(size_t)NN * DD];  // fp16 per-layer outputs
__device__ int    g_count[NN];       // zero at load; drained back to 0 by k_place
__device__ int    g_rowptr[NN + 1];
__device__ int    g_bsum[SCAN_NBLK];
__device__ __align__(16) int2 g_edges[NE];          // packed {col, val-bits}

__device__ __forceinline__ float sigmoidf(float x) {
    return 1.0f / (1.0f + __expf(-x));
}
__device__ __forceinline__ unsigned int h2_to_u(__half2 h) {
    return *reinterpret_cast<unsigned int*>(&h);
}
__device__ __forceinline__ __half2 u_to_h2(unsigned int u) {
    return *reinterpret_cast<__half2*>(&u);
}

// ---------------------------------------------------------------------------
// Fused layer-0 + row histogram (g_count is 0 on entry every call).
// ---------------------------------------------------------------------------
__global__ void k_fuse0count(const float* __restrict__ ue, const float* __restrict__ ie,
                             const float* __restrict__ se, const float* __restrict__ he,
                             const float* __restrict__ ulw, const float* __restrict__ ilw,
                             const int* __restrict__ er) {
    int idx = blockIdx.x * blockDim.x + threadIdx.x;
    if (idx < NE) atomicAdd(&g_count[er[idx]], 1);
    const int n4 = NN * DD / 4;
    if (idx >= n4) return;
    float4 r;
    if (idx < NU * DD / 4) {
        float a = sigmoidf(ulw[0]);
        float4 x = ((const float4*)ue)[idx];
        float4 s = ((const float4*)se)[idx];
        r.x = a * x.x + (1.0f - a) * s.x;
        r.y = a * x.y + (1.0f - a) * s.y;
        r.z = a * x.z + (1.0f - a) * s.z;
        r.w = a * x.w + (1.0f - a) * s.w;
    } else {
        int j = idx - NU * DD / 4;
        float b = sigmoidf(ilw[0]);
        float4 x = ((const float4*)ie)[j];
        float4 h = ((const float4*)he)[j];
        r.x = b * x.x + (1.0f - b) * h.x;
        r.y = b * x.y + (1.0f - b) * h.y;
        r.z = b * x.z + (1.0f - b) * h.z;
        r.w = b * x.w + (1.0f - b) * h.w;
    }
    uint2 hp;
    hp.x = h2_to_u(__floats2half2_rn(r.x, r.y));
    hp.y = h2_to_u(__floats2half2_rn(r.z, r.w));
    ((uint2*)g_embs[0])[idx] = hp;
}

// ---------------------------------------------------------------------------
// CSR scan (R6-proven 3-kernel pipeline)
// ---------------------------------------------------------------------------
__global__ void k_scan_blocks() {
    __shared__ int sh[SCAN_BS];
    int i = blockIdx.x * SCAN_BS + threadIdx.x;
    int v = (i < NN) ? g_count[i] : 0;
    sh[threadIdx.x] = v;
    __syncthreads();
    #pragma unroll
    for (int o = 1; o < SCAN_BS; o <<= 1) {
        int t = (threadIdx.x >= o) ? sh[threadIdx.x - o] : 0;
        __syncthreads();
        sh[threadIdx.x] += t;
        __syncthreads();
    }
    if (i < NN) g_rowptr[i] = sh[threadIdx.x] - v;
    if (threadIdx.x == SCAN_BS - 1) g_bsum[blockIdx.x] = sh[SCAN_BS - 1];
}

__global__ void k_scan_tops() {
    __shared__ int sh[SCAN_BS];
    int v = (threadIdx.x < SCAN_NBLK) ? g_bsum[threadIdx.x] : 0;
    sh[threadIdx.x] = v;
    __syncthreads();
    #pragma unroll
    for (int o = 1; o < SCAN_BS; o <<= 1) {
        int t = (threadIdx.x >= o) ? sh[threadIdx.x - o] : 0;
        __syncthreads();
        sh[threadIdx.x] += t;
        __syncthreads();
    }
    if (threadIdx.x < SCAN_NBLK) g_bsum[threadIdx.x] = sh[threadIdx.x] - v;
}

__global__ void k_scan_add() {
    int i = blockIdx.x * blockDim.x + threadIdx.x;
    if (i >= NN) return;
    g_rowptr[i] += g_bsum[i / SCAN_BS];
    if (i == 0) g_rowptr[NN] = NE;
}

// ---------------------------------------------------------------------------
// Place packed {col,val}: position by draining g_count (leaves it 0 for the
// next call — which is what lets k_fuse0count skip the zeroing pass).
// ---------------------------------------------------------------------------
__global__ void k_place(const float* __restrict__ ev, const int* __restrict__ er,
                        const int* __restrict__ ec) {
    int e = blockIdx.x * blockDim.x + threadIdx.x;
    if (e >= NE) return;
    int row = er[e];
    int old = atomicAdd(&g_count[row], -1);       // old in [deg..1]
    int pos = __ldg(&g_rowptr[row]) + old - 1;
    g_edges[pos] = make_int2(ec[e], __float_as_int(ev[e]));
}

// ---------------------------------------------------------------------------
// Gather SpMM (fp16 table, fp32 accumulate) + per-layer fusion.
// 8 threads per row; each handles 8 consecutive dims. (R6-proven inner loop.)
// ---------------------------------------------------------------------------
__global__ void k_spmm_fuse(const float* __restrict__ se, const float* __restrict__ he,
                            const float* __restrict__ ulw, const float* __restrict__ ilw,
                            int layer) {
    int tid = blockIdx.x * blockDim.x + threadIdx.x;
    int row = tid >> 3;
    int c   = tid & 7;
    if (row >= NN) return;

    const uint4* cur  = (const uint4*)g_embs[layer - 1];
    uint4*       next = (uint4*)g_embs[layer];

    int s = __ldg(&g_rowptr[row]);
    int t = __ldg(&g_rowptr[row + 1]);

    float2 s0 = make_float2(0.f, 0.f), s1 = s0, s2 = s0, s3 = s0;

    int e = s;
    for (; e + 4 <= t; e += 4) {
        int2 e0 = __ldg(&g_edges[e + 0]);
        int2 e1 = __ldg(&g_edges[e + 1]);
        int2 e2 = __ldg(&g_edges[e + 2]);
        int2 e3 = __ldg(&g_edges[e + 3]);
        uint4 x0 = __ldg(&cur[e0.x * 8 + c]);
        uint4 x1 = __ldg(&cur[e1.x * 8 + c]);
        uint4 x2 = __ldg(&cur[e2.x * 8 + c]);
        uint4 x3 = __ldg(&cur[e3.x * 8 + c]);
        float v0 = __int_as_float(e0.y), v1 = __int_as_float(e1.y);
        float v2 = __int_as_float(e2.y), v3 = __int_as_float(e3.y);
        float2 f;
        f = __half22float2(u_to_h2(x0.x)); s0.x += v0*f.x; s0.y += v0*f.y;
        f = __half22float2(u_to_h2(x0.y)); s1.x += v0*f.x; s1.y += v0*f.y;
        f = __half22float2(u_to_h2(x0.z)); s2.x += v0*f.x; s2.y += v0*f.y;
        f = __half22float2(u_to_h2(x0.w)); s3.x += v0*f.x; s3.y += v0*f.y;
        f = __half22float2(u_to_h2(x1.x)); s0.x += v1*f.x; s0.y += v1*f.y;
        f = __half22float2(u_to_h2(x1.y)); s1.x += v1*f.x; s1.y += v1*f.y;
        f = __half22float2(u_to_h2(x1.z)); s2.x += v1*f.x; s2.y += v1*f.y;
        f = __half22float2(u_to_h2(x1.w)); s3.x += v1*f.x; s3.y += v1*f.y;
        f = __half22float2(u_to_h2(x2.x)); s0.x += v2*f.x; s0.y += v2*f.y;
        f = __half22float2(u_to_h2(x2.y)); s1.x += v2*f.x; s1.y += v2*f.y;
        f = __half22float2(u_to_h2(x2.z)); s2.x += v2*f.x; s2.y += v2*f.y;
        f = __half22float2(u_to_h2(x2.w)); s3.x += v2*f.x; s3.y += v2*f.y;
        f = __half22float2(u_to_h2(x3.x)); s0.x += v3*f.x; s0.y += v3*f.y;
        f = __half22float2(u_to_h2(x3.y)); s1.x += v3*f.x; s1.y += v3*f.y;
        f = __half22float2(u_to_h2(x3.z)); s2.x += v3*f.x; s2.y += v3*f.y;
        f = __half22float2(u_to_h2(x3.w)); s3.x += v3*f.x; s3.y += v3*f.y;
    }
    for (; e < t; e++) {
        int2 ed = __ldg(&g_edges[e]);
        uint4 x = __ldg(&cur[ed.x * 8 + c]);
        float v = __int_as_float(ed.y);
        float2 f;
        f = __half22float2(u_to_h2(x.x)); s0.x += v*f.x; s0.y += v*f.y;
        f = __half22float2(u_to_h2(x.y)); s1.x += v*f.x; s1.y += v*f.y;
        f = __half22float2(u_to_h2(x.z)); s2.x += v*f.x; s2.y += v*f.y;
        f = __half22float2(u_to_h2(x.w)); s3.x += v*f.x; s3.y += v*f.y;
    }

    bool isU = row < NU;
    float w = sigmoidf(isU ? ulw[layer] : ilw[layer]);
    float omw = 1.0f - w;
    const float4* sdp = isU ? (const float4*)se + (size_t)row * 16 + c * 2
                            : (const float4*)he + (size_t)(row - NU) * 16 + c * 2;
    float4 sa = __ldg(sdp);
    float4 sb = __ldg(sdp + 1);

    uint4 hout;
    hout.x = h2_to_u(__floats2half2_rn(w * s0.x + omw * sa.x, w * s0.y + omw * sa.y));
    hout.y = h2_to_u(__floats2half2_rn(w * s1.x + omw * sa.z, w * s1.y + omw * sa.w));
    hout.z = h2_to_u(__floats2half2_rn(w * s2.x + omw * sb.x, w * s2.y + omw * sb.y));
    hout.w = h2_to_u(__floats2half2_rn(w * s3.x + omw * sb.z, w * s3.y + omw * sb.w));
    next[row * 8 + c] = hout;
}

// ---------------------------------------------------------------------------
// Final dot over on-the-fly 4-layer sum.
// ---------------------------------------------------------------------------
__global__ void k_dot(const int* __restrict__ users, const int* __restrict__ items,
                      float* __restrict__ out) {
    int w = (blockIdx.x * blockDim.x + threadIdx.x) >> 5;
    int l = threadIdx.x & 31;
    if (w >= NB) return;
    size_t uo = (size_t)users[w] * 32 + l;
    size_t io = (size_t)(NU + items[w]) * 32 + l;
    float ux = 0.f, uy = 0.f, ix = 0.f, iy = 0.f;
    #pragma unroll
    for (int L = 0; L <= NL; L++) {
        float2 fu = __half22float2(((const __half2*)g_embs[L])[uo]);
        float2 fi = __half22float2(((const __half2*)g_embs[L])[io]);
        ux += fu.x; uy += fu.y;
        ix += fi.x; iy += fi.y;
    }
    float s = ux * ix + uy * iy;
    #pragma unroll
    for (int o = 16; o > 0; o >>= 1)
        s += __shfl_down_sync(0xffffffffu, s, o);
    if (l == 0) out[w] = s * (1.0f / 16.0f);
}

extern "C" void kernel_launch(void* const* d_in, const int* in_sizes, int n_in,
                              void* d_out, int out_size) {
    const float* user_emb    = (const float*)d_in[0];
    const float* item_emb    = (const float*)d_in[1];
    const float* symptom_emb = (const float*)d_in[2];
    const float* herb_emb    = (const float*)d_in[3];
    const float* user_lw     = (const float*)d_in[4];
    const float* item_lw     = (const float*)d_in[5];
    const float* edge_val    = (const float*)d_in[6];
    const int*   edge_row    = (const int*)d_in[7];
    const int*   edge_col    = (const int*)d_in[8];
    const int*   users       = (const int*)d_in[9];
    const int*   items       = (const int*)d_in[10];
    float* out = (float*)d_out;

    const int TB = 256;
    const int gEdge = (NE + TB - 1) / TB;
    const int gRow  = (NN * 8 + TB - 1) / TB;

    k_fuse0count<<<gEdge, TB>>>(user_emb, item_emb, symptom_emb, herb_emb,
                                user_lw, item_lw, edge_row);
    k_scan_blocks<<<SCAN_NBLK, SCAN_BS>>>();
    k_scan_tops<<<1, SCAN_BS>>>();
    k_scan_add<<<(NN + TB - 1) / TB, TB>>>();
    k_place<<<gEdge, TB>>>(edge_val, edge_row, edge_col);

    for (int layer = 1; layer <= NL; layer++) {
        k_spmm_fuse<<<gRow, TB>>>(symptom_emb, herb_emb, user_lw, item_lw, layer);
    }
    k_dot<<<(NB * 32 + TB - 1) / TB, TB>>>(users, items, out);
}

// round 12
// speedup vs baseline: 1.1245x; 1.0414x over previous
#include <cuda_runtime.h>
#include <cuda_fp16.h>

#define NU 100000
#define NI 100000
#define DD 64
#define NL 3
#define NE 6400000
#define NB 16384
#define NN (NU + NI)

#define SCAN_BS 512
#define SCAN_NBLK ((NN + SCAN_BS - 1) / SCAN_BS)   // 391

// Scratch — __device__ globals, no allocation.
__device__ __half g_embs[NL + 1][(size_t)NN * DD];  // fp16 per-layer outputs
__device__ int    g_count[NN];
__device__ int    g_rowptr[NN + 1];
__device__ int    g_woff[NN];
__device__ int    g_bsum[SCAN_NBLK];                // per-scan-block totals (unscanned)
__device__ __align__(16) int2 g_edges[NE];          // packed {col, val-bits}

__device__ __forceinline__ float sigmoidf(float x) {
    return 1.0f / (1.0f + __expf(-x));
}
__device__ __forceinline__ unsigned int h2_to_u(__half2 h) {
    return *reinterpret_cast<unsigned int*>(&h);
}
__device__ __forceinline__ __half2 u_to_h2(unsigned int u) {
    return *reinterpret_cast<__half2*>(&u);
}

// ---------------------------------------------------------------------------
// Layer-0 fusion + zero row counters. g_embs[0](fp16) = fused layer-0.
// ---------------------------------------------------------------------------
__global__ void k_fuse0(const float* __restrict__ ue, const float* __restrict__ ie,
                        const float* __restrict__ se, const float* __restrict__ he,
                        const float* __restrict__ ulw, const float* __restrict__ ilw) {
    int idx = blockIdx.x * blockDim.x + threadIdx.x;
    if (idx < NN) g_count[idx] = 0;
    const int n4 = NN * DD / 4;
    if (idx >= n4) return;
    float4 r;
    if (idx < NU * DD / 4) {
        float a = sigmoidf(ulw[0]);
        float4 x = ((const float4*)ue)[idx];
        float4 s = ((const float4*)se)[idx];
        r.x = a * x.x + (1.0f - a) * s.x;
        r.y = a * x.y + (1.0f - a) * s.y;
        r.z = a * x.z + (1.0f - a) * s.z;
        r.w = a * x.w + (1.0f - a) * s.w;
    } else {
        int j = idx - NU * DD / 4;
        float b = sigmoidf(ilw[0]);
        float4 x = ((const float4*)ie)[j];
        float4 h = ((const float4*)he)[j];
        r.x = b * x.x + (1.0f - b) * h.x;
        r.y = b * x.y + (1.0f - b) * h.y;
        r.z = b * x.z + (1.0f - b) * h.z;
        r.w = b * x.w + (1.0f - b) * h.w;
    }
    uint2 hp;
    hp.x = h2_to_u(__floats2half2_rn(r.x, r.y));
    hp.y = h2_to_u(__floats2half2_rn(r.z, r.w));
    ((uint2*)g_embs[0])[idx] = hp;
}

// ---------------------------------------------------------------------------
// CSR build
// ---------------------------------------------------------------------------
__global__ void k_count(const int* __restrict__ er) {
    int e = blockIdx.x * blockDim.x + threadIdx.x;
    if (e >= NE) return;
    atomicAdd(&g_count[er[e]], 1);
}

__global__ void k_scan_blocks() {
    __shared__ int sh[SCAN_BS];
    int i = blockIdx.x * SCAN_BS + threadIdx.x;
    int v = (i < NN) ? g_count[i] : 0;
    sh[threadIdx.x] = v;
    __syncthreads();
    #pragma unroll
    for (int o = 1; o < SCAN_BS; o <<= 1) {
        int t = (threadIdx.x >= o) ? sh[threadIdx.x - o] : 0;
        __syncthreads();
        sh[threadIdx.x] += t;
        __syncthreads();
    }
    if (i < NN) g_rowptr[i] = sh[threadIdx.x] - v;   // block-local exclusive
    if (threadIdx.x == SCAN_BS - 1) g_bsum[blockIdx.x] = sh[SCAN_BS - 1];
}

// Merged scan_tops + scan_add: each 256-thread block lies inside ONE 512-wide
// scan block, so warp 0 computes the single needed prefix of g_bsum directly.
__global__ void k_scan_add() {
    __shared__ int s_off;
    int b = blockIdx.x;
    int sb = (b * 256) >> 9;              // owning scan-block index
    if (threadIdx.x < 32) {
        int acc = 0;
        for (int j = threadIdx.x; j < sb; j += 32) acc += g_bsum[j];
        #pragma unroll
        for (int o = 16; o > 0; o >>= 1)
            acc += __shfl_down_sync(0xffffffffu, acc, o);
        if (threadIdx.x == 0) s_off = acc;
    }
    __syncthreads();
    int i = b * 256 + threadIdx.x;
    if (i >= NN) return;
    int p = g_rowptr[i] + s_off;
    g_rowptr[i] = p;
    g_woff[i] = p;
    if (i == 0) g_rowptr[NN] = NE;
}

__global__ void k_place(const float* __restrict__ ev, const int* __restrict__ er,
                        const int* __restrict__ ec) {
    int e = blockIdx.x * blockDim.x + threadIdx.x;
    if (e >= NE) return;
    int row = er[e];
    int pos = atomicAdd(&g_woff[row], 1);
    g_edges[pos] = make_int2(ec[e], __float_as_int(ev[e]));
}

// ---------------------------------------------------------------------------
// Gather SpMM (fp16 table, fp32 accumulate) + per-layer fusion.
// 8 threads per row; each handles 8 consecutive dims. (R6-proven inner loop.)
// ---------------------------------------------------------------------------
__global__ void k_spmm_fuse(const float* __restrict__ se, const float* __restrict__ he,
                            const float* __restrict__ ulw, const float* __restrict__ ilw,
                            int layer) {
    int tid = blockIdx.x * blockDim.x + threadIdx.x;
    int row = tid >> 3;
    int c   = tid & 7;
    if (row >= NN) return;

    const uint4* cur  = (const uint4*)g_embs[layer - 1];
    uint4*       next = (uint4*)g_embs[layer];

    int s = __ldg(&g_rowptr[row]);
    int t = __ldg(&g_rowptr[row + 1]);

    float2 s0 = make_float2(0.f, 0.f), s1 = s0, s2 = s0, s3 = s0;

    int e = s;
    for (; e + 4 <= t; e += 4) {
        int2 e0 = __ldg(&g_edges[e + 0]);
        int2 e1 = __ldg(&g_edges[e + 1]);
        int2 e2 = __ldg(&g_edges[e + 2]);
        int2 e3 = __ldg(&g_edges[e + 3]);
        uint4 x0 = __ldg(&cur[e0.x * 8 + c]);
        uint4 x1 = __ldg(&cur[e1.x * 8 + c]);
        uint4 x2 = __ldg(&cur[e2.x * 8 + c]);
        uint4 x3 = __ldg(&cur[e3.x * 8 + c]);
        float v0 = __int_as_float(e0.y), v1 = __int_as_float(e1.y);
        float v2 = __int_as_float(e2.y), v3 = __int_as_float(e3.y);
        float2 f;
        f = __half22float2(u_to_h2(x0.x)); s0.x += v0*f.x; s0.y += v0*f.y;
        f = __half22float2(u_to_h2(x0.y)); s1.x += v0*f.x; s1.y += v0*f.y;
        f = __half22float2(u_to_h2(x0.z)); s2.x += v0*f.x; s2.y += v0*f.y;
        f = __half22float2(u_to_h2(x0.w)); s3.x += v0*f.x; s3.y += v0*f.y;
        f = __half22float2(u_to_h2(x1.x)); s0.x += v1*f.x; s0.y += v1*f.y;
        f = __half22float2(u_to_h2(x1.y)); s1.x += v1*f.x; s1.y += v1*f.y;
        f = __half22float2(u_to_h2(x1.z)); s2.x += v1*f.x; s2.y += v1*f.y;
        f = __half22float2(u_to_h2(x1.w)); s3.x += v1*f.x; s3.y += v1*f.y;
        f = __half22float2(u_to_h2(x2.x)); s0.x += v2*f.x; s0.y += v2*f.y;
        f = __half22float2(u_to_h2(x2.y)); s1.x += v2*f.x; s1.y += v2*f.y;
        f = __half22float2(u_to_h2(x2.z)); s2.x += v2*f.x; s2.y += v2*f.y;
        f = __half22float2(u_to_h2(x2.w)); s3.x += v2*f.x; s3.y += v2*f.y;
        f = __half22float2(u_to_h2(x3.x)); s0.x += v3*f.x; s0.y += v3*f.y;
        f = __half22float2(u_to_h2(x3.y)); s1.x += v3*f.x; s1.y += v3*f.y;
        f = __half22float2(u_to_h2(x3.z)); s2.x += v3*f.x; s2.y += v3*f.y;
        f = __half22float2(u_to_h2(x3.w)); s3.x += v3*f.x; s3.y += v3*f.y;
    }
    for (; e < t; e++) {
        int2 ed = __ldg(&g_edges[e]);
        uint4 x = __ldg(&cur[ed.x * 8 + c]);
        float v = __int_as_float(ed.y);
        float2 f;
        f = __half22float2(u_to_h2(x.x)); s0.x += v*f.x; s0.y += v*f.y;
        f = __half22float2(u_to_h2(x.y)); s1.x += v*f.x; s1.y += v*f.y;
        f = __half22float2(u_to_h2(x.z)); s2.x += v*f.x; s2.y += v*f.y;
        f = __half22float2(u_to_h2(x.w)); s3.x += v*f.x; s3.y += v*f.y;
    }

    bool isU = row < NU;
    float w = sigmoidf(isU ? ulw[layer] : ilw[layer]);
    float omw = 1.0f - w;
    const float4* sdp = isU ? (const float4*)se + (size_t)row * 16 + c * 2
                            : (const float4*)he + (size_t)(row - NU) * 16 + c * 2;
    float4 sa = __ldg(sdp);
    float4 sb = __ldg(sdp + 1);

    uint4 hout;
    hout.x = h2_to_u(__floats2half2_rn(w * s0.x + omw * sa.x, w * s0.y + omw * sa.y));
    hout.y = h2_to_u(__floats2half2_rn(w * s1.x + omw * sa.z, w * s1.y + omw * sa.w));
    hout.z = h2_to_u(__floats2half2_rn(w * s2.x + omw * sb.x, w * s2.y + omw * sb.y));
    hout.w = h2_to_u(__floats2half2_rn(w * s3.x + omw * sb.z, w * s3.y + omw * sb.w));
    next[row * 8 + c] = hout;
}

// ---------------------------------------------------------------------------
// Final dot over on-the-fly 4-layer sum.
// ---------------------------------------------------------------------------
__global__ void k_dot(const int* __restrict__ users, const int* __restrict__ items,
                      float* __restrict__ out) {
    int w = (blockIdx.x * blockDim.x + threadIdx.x) >> 5;
    int l = threadIdx.x & 31;
    if (w >= NB) return;
    size_t uo = (size_t)users[w] * 32 + l;
    size_t io = (size_t)(NU + items[w]) * 32 + l;
    float ux = 0.f, uy = 0.f, ix = 0.f, iy = 0.f;
    #pragma unroll
    for (int L = 0; L <= NL; L++) {
        float2 fu = __half22float2(((const __half2*)g_embs[L])[uo]);
        float2 fi = __half22float2(((const __half2*)g_embs[L])[io]);
        ux += fu.x; uy += fu.y;
        ix += fi.x; iy += fi.y;
    }
    float s = ux * ix + uy * iy;
    #pragma unroll
    for (int o = 16; o > 0; o >>= 1)
        s += __shfl_down_sync(0xffffffffu, s, o);
    if (l == 0) out[w] = s * (1.0f / 16.0f);
}

extern "C" void kernel_launch(void* const* d_in, const int* in_sizes, int n_in,
                              void* d_out, int out_size) {
    const float* user_emb    = (const float*)d_in[0];
    const float* item_emb    = (const float*)d_in[1];
    const float* symptom_emb = (const float*)d_in[2];
    const float* herb_emb    = (const float*)d_in[3];
    const float* user_lw     = (const float*)d_in[4];
    const float* item_lw     = (const float*)d_in[5];
    const float* edge_val    = (const float*)d_in[6];
    const int*   edge_row    = (const int*)d_in[7];
    const int*   edge_col    = (const int*)d_in[8];
    const int*   users       = (const int*)d_in[9];
    const int*   items       = (const int*)d_in[10];
    float* out = (float*)d_out;

    const int n4 = NN * DD / 4;
    const int TB = 256;
    const int gElem = (n4 + TB - 1) / TB;
    const int gEdge = (NE + TB - 1) / TB;
    const int gRow  = (NN * 8 + TB - 1) / TB;

    k_fuse0<<<gElem, TB>>>(user_emb, item_emb, symptom_emb, herb_emb, user_lw, item_lw);
    k_count<<<gEdge, TB>>>(edge_row);
    k_scan_blocks<<<SCAN_NBLK, SCAN_BS>>>();
    k_scan_add<<<(NN + TB - 1) / TB, TB>>>();
    k_place<<<gEdge, TB>>>(edge_val, edge_row, edge_col);

    for (int layer = 1; layer <= NL; layer++) {
        k_spmm_fuse<<<gRow, TB>>>(symptom_emb, herb_emb, user_lw, item_lw, layer);
    }
    k_dot<<<(NB * 32 + TB - 1) / TB, TB>>>(users, items, out);
}

// round 14
// speedup vs baseline: 1.1257x; 1.0011x over previous
#include <cuda_runtime.h>
#include <cuda_fp16.h>

#define NU 100000
#define NI 100000
#define DD 64
#define NL 3
#define NE 6400000
#define NB 16384
#define NN (NU + NI)

#define SCAN_BS 512
#define SCAN_NBLK ((NN + SCAN_BS - 1) / SCAN_BS)   // 391

// Scratch — __device__ globals, no allocation.
__device__ __half g_embs[NL + 1][(size_t)NN * DD];  // fp16 per-layer outputs
__device__ __half g_side[(size_t)NN * DD];          // fp16 concat(symptom, herb)
__device__ int    g_count[NN];
__device__ int    g_rowptr[NN + 1];
__device__ int    g_woff[NN];
__device__ int    g_bsum[SCAN_NBLK];                // per-scan-block totals (unscanned)
__device__ __align__(16) int2 g_edges[NE];          // packed {col, val-bits}

__device__ __forceinline__ float sigmoidf(float x) {
    return 1.0f / (1.0f + __expf(-x));
}
__device__ __forceinline__ unsigned int h2_to_u(__half2 h) {
    return *reinterpret_cast<unsigned int*>(&h);
}
__device__ __forceinline__ __half2 u_to_h2(unsigned int u) {
    return *reinterpret_cast<__half2*>(&u);
}

// ---------------------------------------------------------------------------
// Layer-0 fusion + fp16 side table + zero row counters.
// ---------------------------------------------------------------------------
__global__ void k_fuse0(const float* __restrict__ ue, const float* __restrict__ ie,
                        const float* __restrict__ se, const float* __restrict__ he,
                        const float* __restrict__ ulw, const float* __restrict__ ilw) {
    int idx = blockIdx.x * blockDim.x + threadIdx.x;
    if (idx < NN) g_count[idx] = 0;
    const int n4 = NN * DD / 4;
    if (idx >= n4) return;
    float4 r, sd;
    if (idx < NU * DD / 4) {
        float a = sigmoidf(ulw[0]);
        float4 x = ((const float4*)ue)[idx];
        sd = ((const float4*)se)[idx];
        r.x = a * x.x + (1.0f - a) * sd.x;
        r.y = a * x.y + (1.0f - a) * sd.y;
        r.z = a * x.z + (1.0f - a) * sd.z;
        r.w = a * x.w + (1.0f - a) * sd.w;
    } else {
        int j = idx - NU * DD / 4;
        float b = sigmoidf(ilw[0]);
        float4 x = ((const float4*)ie)[j];
        sd = ((const float4*)he)[j];
        r.x = b * x.x + (1.0f - b) * sd.x;
        r.y = b * x.y + (1.0f - b) * sd.y;
        r.z = b * x.z + (1.0f - b) * sd.z;
        r.w = b * x.w + (1.0f - b) * sd.w;
    }
    uint2 hp;
    hp.x = h2_to_u(__floats2half2_rn(r.x, r.y));
    hp.y = h2_to_u(__floats2half2_rn(r.z, r.w));
    ((uint2*)g_embs[0])[idx] = hp;
    uint2 hs;
    hs.x = h2_to_u(__floats2half2_rn(sd.x, sd.y));
    hs.y = h2_to_u(__floats2half2_rn(sd.z, sd.w));
    ((uint2*)g_side)[idx] = hs;
}

// ---------------------------------------------------------------------------
// CSR build — vectorized histogram (NE % 4 == 0)
// ---------------------------------------------------------------------------
__global__ void k_count(const int* __restrict__ er) {
    int i = blockIdx.x * blockDim.x + threadIdx.x;
    if (i >= NE / 4) return;
    int4 r = __ldg(&((const int4*)er)[i]);
    atomicAdd(&g_count[r.x], 1);
    atomicAdd(&g_count[r.y], 1);
    atomicAdd(&g_count[r.z], 1);
    atomicAdd(&g_count[r.w], 1);
}

__global__ void k_scan_blocks() {
    __shared__ int sh[SCAN_BS];
    int i = blockIdx.x * SCAN_BS + threadIdx.x;
    int v = (i < NN) ? g_count[i] : 0;
    sh[threadIdx.x] = v;
    __syncthreads();
    #pragma unroll
    for (int o = 1; o < SCAN_BS; o <<= 1) {
        int t = (threadIdx.x >= o) ? sh[threadIdx.x - o] : 0;
        __syncthreads();
        sh[threadIdx.x] += t;
        __syncthreads();
    }
    if (i < NN) g_rowptr[i] = sh[threadIdx.x] - v;   // block-local exclusive
    if (threadIdx.x == SCAN_BS - 1) g_bsum[blockIdx.x] = sh[SCAN_BS - 1];
}

// Merged scan_tops + scan_add (R12-proven).
__global__ void k_scan_add() {
    __shared__ int s_off;
    int b = blockIdx.x;
    int sb = (b * 256) >> 9;              // owning scan-block index
    if (threadIdx.x < 32) {
        int acc = 0;
        for (int j = threadIdx.x; j < sb; j += 32) acc += g_bsum[j];
        #pragma unroll
        for (int o = 16; o > 0; o >>= 1)
            acc += __shfl_down_sync(0xffffffffu, acc, o);
        if (threadIdx.x == 0) s_off = acc;
    }
    __syncthreads();
    int i = b * 256 + threadIdx.x;
    if (i >= NN) return;
    int p = g_rowptr[i] + s_off;
    g_rowptr[i] = p;
    g_woff[i] = p;
    if (i == 0) g_rowptr[NN] = NE;
}

// Vectorized placement: 4 edges per thread (NE % 4 == 0).
__global__ void k_place(const float* __restrict__ ev, const int* __restrict__ er,
                        const int* __restrict__ ec) {
    int i = blockIdx.x * blockDim.x + threadIdx.x;
    if (i >= NE / 4) return;
    int4   rr = __ldg(&((const int4*)er)[i]);
    int4   cc = __ldg(&((const int4*)ec)[i]);
    float4 vv = __ldg(&((const float4*)ev)[i]);
    int p0 = atomicAdd(&g_woff[rr.x], 1);
    g_edges[p0] = make_int2(cc.x, __float_as_int(vv.x));
    int p1 = atomicAdd(&g_woff[rr.y], 1);
    g_edges[p1] = make_int2(cc.y, __float_as_int(vv.y));
    int p2 = atomicAdd(&g_woff[rr.z], 1);
    g_edges[p2] = make_int2(cc.z, __float_as_int(vv.z));
    int p3 = atomicAdd(&g_woff[rr.w], 1);
    g_edges[p3] = make_int2(cc.w, __float_as_int(vv.w));
}

// ---------------------------------------------------------------------------
// Gather SpMM (fp16 table, fp32 accumulate) + per-layer fusion.
// 8 threads per row; each handles 8 consecutive dims. fp16 side table.
// ---------------------------------------------------------------------------
__global__ void k_spmm_fuse(const float* __restrict__ ulw, const float* __restrict__ ilw,
                            int layer) {
    int tid = blockIdx.x * blockDim.x + threadIdx.x;
    int row = tid >> 3;
    int c   = tid & 7;
    if (row >= NN) return;

    const uint4* cur  = (const uint4*)g_embs[layer - 1];
    uint4*       next = (uint4*)g_embs[layer];

    int s = __ldg(&g_rowptr[row]);
    int t = __ldg(&g_rowptr[row + 1]);

    float2 s0 = make_float2(0.f, 0.f), s1 = s0, s2 = s0, s3 = s0;

    int e = s;
    for (; e + 4 <= t; e += 4) {
        int2 e0 = __ldg(&g_edges[e + 0]);
        int2 e1 = __ldg(&g_edges[e + 1]);
        int2 e2 = __ldg(&g_edges[e + 2]);
        int2 e3 = __ldg(&g_edges[e + 3]);
        uint4 x0 = __ldg(&cur[e0.x * 8 + c]);
        uint4 x1 = __ldg(&cur[e1.x * 8 + c]);
        uint4 x2 = __ldg(&cur[e2.x * 8 + c]);
        uint4 x3 = __ldg(&cur[e3.x * 8 + c]);
        float v0 = __int_as_float(e0.y), v1 = __int_as_float(e1.y);
        float v2 = __int_as_float(e2.y), v3 = __int_as_float(e3.y);
        float2 f;
        f = __half22float2(u_to_h2(x0.x)); s0.x += v0*f.x; s0.y += v0*f.y;
        f = __half22float2(u_to_h2(x0.y)); s1.x += v0*f.x; s1.y += v0*f.y;
        f = __half22float2(u_to_h2(x0.z)); s2.x += v0*f.x; s2.y += v0*f.y;
        f = __half22float2(u_to_h2(x0.w)); s3.x += v0*f.x; s3.y += v0*f.y;
        f = __half22float2(u_to_h2(x1.x)); s0.x += v1*f.x; s0.y += v1*f.y;
        f = __half22float2(u_to_h2(x1.y)); s1.x += v1*f.x; s1.y += v1*f.y;
        f = __half22float2(u_to_h2(x1.z)); s2.x += v1*f.x; s2.y += v1*f.y;
        f = __half22float2(u_to_h2(x1.w)); s3.x += v1*f.x; s3.y += v1*f.y;
        f = __half22float2(u_to_h2(x2.x)); s0.x += v2*f.x; s0.y += v2*f.y;
        f = __half22float2(u_to_h2(x2.y)); s1.x += v2*f.x; s1.y += v2*f.y;
        f = __half22float2(u_to_h2(x2.z)); s2.x += v2*f.x; s2.y += v2*f.y;
        f = __half22float2(u_to_h2(x2.w)); s3.x += v2*f.x; s3.y += v2*f.y;
        f = __half22float2(u_to_h2(x3.x)); s0.x += v3*f.x; s0.y += v3*f.y;
        f = __half22float2(u_to_h2(x3.y)); s1.x += v3*f.x; s1.y += v3*f.y;
        f = __half22float2(u_to_h2(x3.z)); s2.x += v3*f.x; s2.y += v3*f.y;
        f = __half22float2(u_to_h2(x3.w)); s3.x += v3*f.x; s3.y += v3*f.y;
    }
    for (; e < t; e++) {
        int2 ed = __ldg(&g_edges[e]);
        uint4 x = __ldg(&cur[ed.x * 8 + c]);
        float v = __int_as_float(ed.y);
        float2 f;
        f = __half22float2(u_to_h2(x.x)); s0.x += v*f.x; s0.y += v*f.y;
        f = __half22float2(u_to_h2(x.y)); s1.x += v*f.x; s1.y += v*f.y;
        f = __half22float2(u_to_h2(x.z)); s2.x += v*f.x; s2.y += v*f.y;
        f = __half22float2(u_to_h2(x.w)); s3.x += v*f.x; s3.y += v*f.y;
    }

    bool isU = row < NU;
    float w = sigmoidf(isU ? ulw[layer] : ilw[layer]);
    float omw = 1.0f - w;
    uint4 sh16 = __ldg((const uint4*)g_side + (size_t)row * 8 + c);
    float2 d0 = __half22float2(u_to_h2(sh16.x));
    float2 d1 = __half22float2(u_to_h2(sh16.y));
    float2 d2 = __half22float2(u_to_h2(sh16.z));
    float2 d3 = __half22float2(u_to_h2(sh16.w));

    uint4 hout;
    hout.x = h2_to_u(__floats2half2_rn(w * s0.x + omw * d0.x, w * s0.y + omw * d0.y));
    hout.y = h2_to_u(__floats2half2_rn(w * s1.x + omw * d1.x, w * s1.y + omw * d1.y));
    hout.z = h2_to_u(__floats2half2_rn(w * s2.x + omw * d2.x, w * s2.y + omw * d2.y));
    hout.w = h2_to_u(__floats2half2_rn(w * s3.x + omw * d3.x, w * s3.y + omw * d3.y));
    next[row * 8 + c] = hout;
}

// ---------------------------------------------------------------------------
// Final dot over on-the-fly 4-layer sum.
// ---------------------------------------------------------------------------
__global__ void k_dot(const int* __restrict__ users, const int* __restrict__ items,
                      float* __restrict__ out) {
    int w = (blockIdx.x * blockDim.x + threadIdx.x) >> 5;
    int l = threadIdx.x & 31;
    if (w >= NB) return;
    size_t uo = (size_t)users[w] * 32 + l;
    size_t io = (size_t)(NU + items[w]) * 32 + l;
    float ux = 0.f, uy = 0.f, ix = 0.f, iy = 0.f;
    #pragma unroll
    for (int L = 0; L <= NL; L++) {
        float2 fu = __half22float2(((const __half2*)g_embs[L])[uo]);
        float2 fi = __half22float2(((const __half2*)g_embs[L])[io]);
        ux += fu.x; uy += fu.y;
        ix += fi.x; iy += fi.y;
    }
    float s = ux * ix + uy * iy;
    #pragma unroll
    for (int o = 16; o > 0; o >>= 1)
        s += __shfl_down_sync(0xffffffffu, s, o);
    if (l == 0) out[w] = s * (1.0f / 16.0f);
}

extern "C" void kernel_launch(void* const* d_in, const int* in_sizes, int n_in,
                              void* d_out, int out_size) {
    const float* user_emb    = (const float*)d_in[0];
    const float* item_emb    = (const float*)d_in[1];
    const float* symptom_emb = (const float*)d_in[2];
    const float* herb_emb    = (const float*)d_in[3];
    const float* user_lw     = (const float*)d_in[4];
    const float* item_lw     = (const float*)d_in[5];
    const float* edge_val    = (const float*)d_in[6];
    const int*   edge_row    = (const int*)d_in[7];
    const int*   edge_col    = (const int*)d_in[8];
    const int*   users       = (const int*)d_in[9];
    const int*   items       = (const int*)d_in[10];
    float* out = (float*)d_out;

    const int n4 = NN * DD / 4;
    const int TB = 256;
    const int gElem  = (n4 + TB - 1) / TB;
    const int gEdge4 = (NE / 4 + TB - 1) / TB;
    const int gRow   = (NN * 8 + TB - 1) / TB;

    k_fuse0<<<gElem, TB>>>(user_emb, item_emb, symptom_emb, herb_emb, user_lw, item_lw);
    k_count<<<gEdge4, TB>>>(edge_row);
    k_scan_blocks<<<SCAN_NBLK, SCAN_BS>>>();
    k_scan_add<<<(NN + TB - 1) / TB, TB>>>();
    k_place<<<gEdge4, TB>>>(edge_val, edge_row, edge_col);

    for (int layer = 1; layer <= NL; layer++) {
        k_spmm_fuse<<<gRow, TB>>>(user_lw, item_lw, layer);
    }
    k_dot<<<(NB * 32 + TB - 1) / TB, TB>>>(users, items, out);
}

// round 15
// speedup vs baseline: 1.2711x; 1.1292x over previous
#include <cuda_runtime.h>
#include <cuda_fp16.h>

#define NU 100000
#define NI 100000
#define DD 64
#define NL 3
#define NE 6400000
#define NB 16384
#define NN (NU + NI)

#define SCAN_BS 512
#define SCAN_NBLK ((NN + SCAN_BS - 1) / SCAN_BS)   // 391

// Scratch — __device__ globals, no allocation.
__device__ __half g_embs[NL + 1][(size_t)NN * DD];  // fp16 per-layer outputs
__device__ __half g_side[(size_t)NN * DD];          // fp16 concat(symptom, herb)
__device__ int    g_count[NN];
__device__ int    g_rowptr[NN + 1];
__device__ int    g_woff[NN];
__device__ int    g_bsum[SCAN_NBLK];                // per-scan-block totals (unscanned)
__device__ __align__(16) int2 g_edges[NE];          // packed {col, val-bits}

__device__ __forceinline__ float sigmoidf(float x) {
    return 1.0f / (1.0f + __expf(-x));
}
__device__ __forceinline__ unsigned int h2_to_u(__half2 h) {
    return *reinterpret_cast<unsigned int*>(&h);
}
__device__ __forceinline__ __half2 u_to_h2(unsigned int u) {
    return *reinterpret_cast<__half2*>(&u);
}

// ---------------------------------------------------------------------------
// Layer-0 fusion + fp16 side table + zero row counters.
// ---------------------------------------------------------------------------
__global__ void k_fuse0(const float* __restrict__ ue, const float* __restrict__ ie,
                        const float* __restrict__ se, const float* __restrict__ he,
                        const float* __restrict__ ulw, const float* __restrict__ ilw) {
    int idx = blockIdx.x * blockDim.x + threadIdx.x;
    if (idx < NN) g_count[idx] = 0;
    const int n4 = NN * DD / 4;
    if (idx >= n4) return;
    float4 r, sd;
    if (idx < NU * DD / 4) {
        float a = sigmoidf(ulw[0]);
        float4 x = ((const float4*)ue)[idx];
        sd = ((const float4*)se)[idx];
        r.x = a * x.x + (1.0f - a) * sd.x;
        r.y = a * x.y + (1.0f - a) * sd.y;
        r.z = a * x.z + (1.0f - a) * sd.z;
        r.w = a * x.w + (1.0f - a) * sd.w;
    } else {
        int j = idx - NU * DD / 4;
        float b = sigmoidf(ilw[0]);
        float4 x = ((const float4*)ie)[j];
        sd = ((const float4*)he)[j];
        r.x = b * x.x + (1.0f - b) * sd.x;
        r.y = b * x.y + (1.0f - b) * sd.y;
        r.z = b * x.z + (1.0f - b) * sd.z;
        r.w = b * x.w + (1.0f - b) * sd.w;
    }
    uint2 hp;
    hp.x = h2_to_u(__floats2half2_rn(r.x, r.y));
    hp.y = h2_to_u(__floats2half2_rn(r.z, r.w));
    ((uint2*)g_embs[0])[idx] = hp;
    uint2 hs;
    hs.x = h2_to_u(__floats2half2_rn(sd.x, sd.y));
    hs.y = h2_to_u(__floats2half2_rn(sd.z, sd.w));
    ((uint2*)g_side)[idx] = hs;
}

// ---------------------------------------------------------------------------
// CSR build — vectorized histogram (NE % 4 == 0)
// ---------------------------------------------------------------------------
__global__ void k_count(const int* __restrict__ er) {
    int i = blockIdx.x * blockDim.x + threadIdx.x;
    if (i >= NE / 4) return;
    int4 r = __ldg(&((const int4*)er)[i]);
    atomicAdd(&g_count[r.x], 1);
    atomicAdd(&g_count[r.y], 1);
    atomicAdd(&g_count[r.z], 1);
    atomicAdd(&g_count[r.w], 1);
}

__global__ void k_scan_blocks() {
    __shared__ int sh[SCAN_BS];
    int i = blockIdx.x * SCAN_BS + threadIdx.x;
    int v = (i < NN) ? g_count[i] : 0;
    sh[threadIdx.x] = v;
    __syncthreads();
    #pragma unroll
    for (int o = 1; o < SCAN_BS; o <<= 1) {
        int t = (threadIdx.x >= o) ? sh[threadIdx.x - o] : 0;
        __syncthreads();
        sh[threadIdx.x] += t;
        __syncthreads();
    }
    if (i < NN) g_rowptr[i] = sh[threadIdx.x] - v;   // block-local exclusive
    if (threadIdx.x == SCAN_BS - 1) g_bsum[blockIdx.x] = sh[SCAN_BS - 1];
}

// Merged scan_tops + scan_add (R12-proven).
__global__ void k_scan_add() {
    __shared__ int s_off;
    int b = blockIdx.x;
    int sb = (b * 256) >> 9;              // owning scan-block index
    if (threadIdx.x < 32) {
        int acc = 0;
        for (int j = threadIdx.x; j < sb; j += 32) acc += g_bsum[j];
        #pragma unroll
        for (int o = 16; o > 0; o >>= 1)
            acc += __shfl_down_sync(0xffffffffu, acc, o);
        if (threadIdx.x == 0) s_off = acc;
    }
    __syncthreads();
    int i = b * 256 + threadIdx.x;
    if (i >= NN) return;
    int p = g_rowptr[i] + s_off;
    g_rowptr[i] = p;
    g_woff[i] = p;
    if (i == 0) g_rowptr[NN] = NE;
}

// Vectorized placement: 4 edges per thread (NE % 4 == 0).
__global__ void k_place(const float* __restrict__ ev, const int* __restrict__ er,
                        const int* __restrict__ ec) {
    int i = blockIdx.x * blockDim.x + threadIdx.x;
    if (i >= NE / 4) return;
    int4   rr = __ldg(&((const int4*)er)[i]);
    int4   cc = __ldg(&((const int4*)ec)[i]);
    float4 vv = __ldg(&((const float4*)ev)[i]);
    int p0 = atomicAdd(&g_woff[rr.x], 1);
    g_edges[p0] = make_int2(cc.x, __float_as_int(vv.x));
    int p1 = atomicAdd(&g_woff[rr.y], 1);
    g_edges[p1] = make_int2(cc.y, __float_as_int(vv.y));
    int p2 = atomicAdd(&g_woff[rr.z], 1);
    g_edges[p2] = make_int2(cc.z, __float_as_int(vv.z));
    int p3 = atomicAdd(&g_woff[rr.w], 1);
    g_edges[p3] = make_int2(cc.w, __float_as_int(vv.w));
}

// ---------------------------------------------------------------------------
// Shared per-row SpMM + fusion body.
// ---------------------------------------------------------------------------
__device__ __forceinline__ void spmm_row(int row, int c, const uint4* cur, uint4* next,
                                         const float* ulw, const float* ilw, int layer) {
    int s = __ldg(&g_rowptr[row]);
    int t = __ldg(&g_rowptr[row + 1]);

    float2 s0 = make_float2(0.f, 0.f), s1 = s0, s2 = s0, s3 = s0;

    int e = s;
    for (; e + 4 <= t; e += 4) {
        int2 e0 = __ldg(&g_edges[e + 0]);
        int2 e1 = __ldg(&g_edges[e + 1]);
        int2 e2 = __ldg(&g_edges[e + 2]);
        int2 e3 = __ldg(&g_edges[e + 3]);
        uint4 x0 = __ldg(&cur[e0.x * 8 + c]);
        uint4 x1 = __ldg(&cur[e1.x * 8 + c]);
        uint4 x2 = __ldg(&cur[e2.x * 8 + c]);
        uint4 x3 = __ldg(&cur[e3.x * 8 + c]);
        float v0 = __int_as_float(e0.y), v1 = __int_as_float(e1.y);
        float v2 = __int_as_float(e2.y), v3 = __int_as_float(e3.y);
        float2 f;
        f = __half22float2(u_to_h2(x0.x)); s0.x += v0*f.x; s0.y += v0*f.y;
        f = __half22float2(u_to_h2(x0.y)); s1.x += v0*f.x; s1.y += v0*f.y;
        f = __half22float2(u_to_h2(x0.z)); s2.x += v0*f.x; s2.y += v0*f.y;
        f = __half22float2(u_to_h2(x0.w)); s3.x += v0*f.x; s3.y += v0*f.y;
        f = __half22float2(u_to_h2(x1.x)); s0.x += v1*f.x; s0.y += v1*f.y;
        f = __half22float2(u_to_h2(x1.y)); s1.x += v1*f.x; s1.y += v1*f.y;
        f = __half22float2(u_to_h2(x1.z)); s2.x += v1*f.x; s2.y += v1*f.y;
        f = __half22float2(u_to_h2(x1.w)); s3.x += v1*f.x; s3.y += v1*f.y;
        f = __half22float2(u_to_h2(x2.x)); s0.x += v2*f.x; s0.y += v2*f.y;
        f = __half22float2(u_to_h2(x2.y)); s1.x += v2*f.x; s1.y += v2*f.y;
        f = __half22float2(u_to_h2(x2.z)); s2.x += v2*f.x; s2.y += v2*f.y;
        f = __half22float2(u_to_h2(x2.w)); s3.x += v2*f.x; s3.y += v2*f.y;
        f = __half22float2(u_to_h2(x3.x)); s0.x += v3*f.x; s0.y += v3*f.y;
        f = __half22float2(u_to_h2(x3.y)); s1.x += v3*f.x; s1.y += v3*f.y;
        f = __half22float2(u_to_h2(x3.z)); s2.x += v3*f.x; s2.y += v3*f.y;
        f = __half22float2(u_to_h2(x3.w)); s3.x += v3*f.x; s3.y += v3*f.y;
    }
    for (; e < t; e++) {
        int2 ed = __ldg(&g_edges[e]);
        uint4 x = __ldg(&cur[ed.x * 8 + c]);
        float v = __int_as_float(ed.y);
        float2 f;
        f = __half22float2(u_to_h2(x.x)); s0.x += v*f.x; s0.y += v*f.y;
        f = __half22float2(u_to_h2(x.y)); s1.x += v*f.x; s1.y += v*f.y;
        f = __half22float2(u_to_h2(x.z)); s2.x += v*f.x; s2.y += v*f.y;
        f = __half22float2(u_to_h2(x.w)); s3.x += v*f.x; s3.y += v*f.y;
    }

    bool isU = row < NU;
    float w = sigmoidf(isU ? ulw[layer] : ilw[layer]);
    float omw = 1.0f - w;
    uint4 sh16 = __ldg((const uint4*)g_side + (size_t)row * 8 + c);
    float2 d0 = __half22float2(u_to_h2(sh16.x));
    float2 d1 = __half22float2(u_to_h2(sh16.y));
    float2 d2 = __half22float2(u_to_h2(sh16.z));
    float2 d3 = __half22float2(u_to_h2(sh16.w));

    uint4 hout;
    hout.x = h2_to_u(__floats2half2_rn(w * s0.x + omw * d0.x, w * s0.y + omw * d0.y));
    hout.y = h2_to_u(__floats2half2_rn(w * s1.x + omw * d1.x, w * s1.y + omw * d1.y));
    hout.z = h2_to_u(__floats2half2_rn(w * s2.x + omw * d2.x, w * s2.y + omw * d2.y));
    hout.w = h2_to_u(__floats2half2_rn(w * s3.x + omw * d3.x, w * s3.y + omw * d3.y));
    next[row * 8 + c] = hout;
}

// Full-graph layer (layers 1..NL-1).
__global__ void k_spmm_fuse(const float* __restrict__ ulw, const float* __restrict__ ilw,
                            int layer) {
    int tid = blockIdx.x * blockDim.x + threadIdx.x;
    int row = tid >> 3;
    int c   = tid & 7;
    if (row >= NN) return;
    spmm_row(row, c, (const uint4*)g_embs[layer - 1], (uint4*)g_embs[layer],
             ulw, ilw, layer);
}

// Final layer: only the sampled rows (users + items). Duplicates write
// identical values — deterministic.
__global__ void k_spmm_fuse_last(const float* __restrict__ ulw, const float* __restrict__ ilw,
                                 const int* __restrict__ users, const int* __restrict__ items) {
    int tid = blockIdx.x * blockDim.x + threadIdx.x;
    int j = tid >> 3;
    int c = tid & 7;
    if (j >= 2 * NB) return;
    int row = (j < NB) ? __ldg(&users[j]) : (NU + __ldg(&items[j - NB]));
    spmm_row(row, c, (const uint4*)g_embs[NL - 1], (uint4*)g_embs[NL],
             ulw, ilw, NL);
}

// ---------------------------------------------------------------------------
// Final dot over on-the-fly 4-layer sum.
// ---------------------------------------------------------------------------
__global__ void k_dot(const int* __restrict__ users, const int* __restrict__ items,
                      float* __restrict__ out) {
    int w = (blockIdx.x * blockDim.x + threadIdx.x) >> 5;
    int l = threadIdx.x & 31;
    if (w >= NB) return;
    size_t uo = (size_t)users[w] * 32 + l;
    size_t io = (size_t)(NU + items[w]) * 32 + l;
    float ux = 0.f, uy = 0.f, ix = 0.f, iy = 0.f;
    #pragma unroll
    for (int L = 0; L <= NL; L++) {
        float2 fu = __half22float2(((const __half2*)g_embs[L])[uo]);
        float2 fi = __half22float2(((const __half2*)g_embs[L])[io]);
        ux += fu.x; uy += fu.y;
        ix += fi.x; iy += fi.y;
    }
    float s = ux * ix + uy * iy;
    #pragma unroll
    for (int o = 16; o > 0; o >>= 1)
        s += __shfl_down_sync(0xffffffffu, s, o);
    if (l == 0) out[w] = s * (1.0f / 16.0f);
}

extern "C" void kernel_launch(void* const* d_in, const int* in_sizes, int n_in,
                              void* d_out, int out_size) {
    const float* user_emb    = (const float*)d_in[0];
    const float* item_emb    = (const float*)d_in[1];
    const float* symptom_emb = (const float*)d_in[2];
    const float* herb_emb    = (const float*)d_in[3];
    const float* user_lw     = (const float*)d_in[4];
    const float* item_lw     = (const float*)d_in[5];
    const float* edge_val    = (const float*)d_in[6];
    const int*   edge_row    = (const int*)d_in[7];
    const int*   edge_col    = (const int*)d_in[8];
    const int*   users       = (const int*)d_in[9];
    const int*   items       = (const int*)d_in[10];
    float* out = (float*)d_out;

    const int n4 = NN * DD / 4;
    const int TB = 256;
    const int gElem  = (n4 + TB - 1) / TB;
    const int gEdge4 = (NE / 4 + TB - 1) / TB;
    const int gRow   = (NN * 8 + TB - 1) / TB;
    const int gLast  = (2 * NB * 8 + TB - 1) / TB;

    k_fuse0<<<gElem, TB>>>(user_emb, item_emb, symptom_emb, herb_emb, user_lw, item_lw);
    k_count<<<gEdge4, TB>>>(edge_row);
    k_scan_blocks<<<SCAN_NBLK, SCAN_BS>>>();
    k_scan_add<<<(NN + TB - 1) / TB, TB>>>();
    k_place<<<gEdge4, TB>>>(edge_val, edge_row, edge_col);

    for (int layer = 1; layer < NL; layer++) {
        k_spmm_fuse<<<gRow, TB>>>(user_lw, item_lw, layer);
    }
    k_spmm_fuse_last<<<gLast, TB>>>(user_lw, item_lw, users, items);
    k_dot<<<(NB * 32 + TB - 1) / TB, TB>>>(users, items, out);
}

// round 16
// speedup vs baseline: 1.2773x; 1.0048x over previous
#include <cuda_runtime.h>
#include <cuda_fp16.h>

#define NU 100000
#define NI 100000
#define DD 64
#define NL 3
#define NE 6400000
#define NB 16384
#define NN (NU + NI)

#define SCAN_BS 512
#define SCAN_NBLK ((NN + SCAN_BS - 1) / SCAN_BS)   // 391

// Scratch — __device__ globals, no allocation.
__device__ __half g_embs[NL + 1][(size_t)NN * DD];  // fp16 per-layer outputs
__device__ __half g_side[(size_t)NN * DD];          // fp16 concat(symptom, herb)
__device__ int    g_count[NN];
__device__ int    g_rowptr[NN + 1];
__device__ int    g_woff[NN];
__device__ int    g_bsum[SCAN_NBLK];                // per-scan-block totals (unscanned)
__device__ __align__(16) int2 g_edges[NE];          // packed {col, val-bits}

__device__ __forceinline__ float sigmoidf(float x) {
    return 1.0f / (1.0f + __expf(-x));
}
__device__ __forceinline__ unsigned int h2_to_u(__half2 h) {
    return *reinterpret_cast<unsigned int*>(&h);
}
__device__ __forceinline__ __half2 u_to_h2(unsigned int u) {
    return *reinterpret_cast<__half2*>(&u);
}

// ---------------------------------------------------------------------------
// Zero row counters (head of the CSR stream).
// ---------------------------------------------------------------------------
__global__ void k_zero_count() {
    int i = blockIdx.x * blockDim.x + threadIdx.x;
    if (i < NN) g_count[i] = 0;
}

// ---------------------------------------------------------------------------
// Layer-0 fusion + fp16 side table (no counter zeroing — runs concurrently
// with the CSR build stream).
// ---------------------------------------------------------------------------
__global__ void k_fuse0(const float* __restrict__ ue, const float* __restrict__ ie,
                        const float* __restrict__ se, const float* __restrict__ he,
                        const float* __restrict__ ulw, const float* __restrict__ ilw) {
    int idx = blockIdx.x * blockDim.x + threadIdx.x;
    const int n4 = NN * DD / 4;
    if (idx >= n4) return;
    float4 r, sd;
    if (idx < NU * DD / 4) {
        float a = sigmoidf(ulw[0]);
        float4 x = ((const float4*)ue)[idx];
        sd = ((const float4*)se)[idx];
        r.x = a * x.x + (1.0f - a) * sd.x;
        r.y = a * x.y + (1.0f - a) * sd.y;
        r.z = a * x.z + (1.0f - a) * sd.z;
        r.w = a * x.w + (1.0f - a) * sd.w;
    } else {
        int j = idx - NU * DD / 4;
        float b = sigmoidf(ilw[0]);
        float4 x = ((const float4*)ie)[j];
        sd = ((const float4*)he)[j];
        r.x = b * x.x + (1.0f - b) * sd.x;
        r.y = b * x.y + (1.0f - b) * sd.y;
        r.z = b * x.z + (1.0f - b) * sd.z;
        r.w = b * x.w + (1.0f - b) * sd.w;
    }
    uint2 hp;
    hp.x = h2_to_u(__floats2half2_rn(r.x, r.y));
    hp.y = h2_to_u(__floats2half2_rn(r.z, r.w));
    ((uint2*)g_embs[0])[idx] = hp;
    uint2 hs;
    hs.x = h2_to_u(__floats2half2_rn(sd.x, sd.y));
    hs.y = h2_to_u(__floats2half2_rn(sd.z, sd.w));
    ((uint2*)g_side)[idx] = hs;
}

// ---------------------------------------------------------------------------
// CSR build — vectorized histogram (NE % 4 == 0)
// ---------------------------------------------------------------------------
__global__ void k_count(const int* __restrict__ er) {
    int i = blockIdx.x * blockDim.x + threadIdx.x;
    if (i >= NE / 4) return;
    int4 r = __ldg(&((const int4*)er)[i]);
    atomicAdd(&g_count[r.x], 1);
    atomicAdd(&g_count[r.y], 1);
    atomicAdd(&g_count[r.z], 1);
    atomicAdd(&g_count[r.w], 1);
}

__global__ void k_scan_blocks() {
    __shared__ int sh[SCAN_BS];
    int i = blockIdx.x * SCAN_BS + threadIdx.x;
    int v = (i < NN) ? g_count[i] : 0;
    sh[threadIdx.x] = v;
    __syncthreads();
    #pragma unroll
    for (int o = 1; o < SCAN_BS; o <<= 1) {
        int t = (threadIdx.x >= o) ? sh[threadIdx.x - o] : 0;
        __syncthreads();
        sh[threadIdx.x] += t;
        __syncthreads();
    }
    if (i < NN) g_rowptr[i] = sh[threadIdx.x] - v;   // block-local exclusive
    if (threadIdx.x == SCAN_BS - 1) g_bsum[blockIdx.x] = sh[SCAN_BS - 1];
}

// Merged scan_tops + scan_add (R12-proven).
__global__ void k_scan_add() {
    __shared__ int s_off;
    int b = blockIdx.x;
    int sb = (b * 256) >> 9;              // owning scan-block index
    if (threadIdx.x < 32) {
        int acc = 0;
        for (int j = threadIdx.x; j < sb; j += 32) acc += g_bsum[j];
        #pragma unroll
        for (int o = 16; o > 0; o >>= 1)
            acc += __shfl_down_sync(0xffffffffu, acc, o);
        if (threadIdx.x == 0) s_off = acc;
    }
    __syncthreads();
    int i = b * 256 + threadIdx.x;
    if (i >= NN) return;
    int p = g_rowptr[i] + s_off;
    g_rowptr[i] = p;
    g_woff[i] = p;
    if (i == 0) g_rowptr[NN] = NE;
}

// Vectorized placement: 4 edges per thread (NE % 4 == 0).
__global__ void k_place(const float* __restrict__ ev, const int* __restrict__ er,
                        const int* __restrict__ ec) {
    int i = blockIdx.x * blockDim.x + threadIdx.x;
    if (i >= NE / 4) return;
    int4   rr = __ldg(&((const int4*)er)[i]);
    int4   cc = __ldg(&((const int4*)ec)[i]);
    float4 vv = __ldg(&((const float4*)ev)[i]);
    int p0 = atomicAdd(&g_woff[rr.x], 1);
    g_edges[p0] = make_int2(cc.x, __float_as_int(vv.x));
    int p1 = atomicAdd(&g_woff[rr.y], 1);
    g_edges[p1] = make_int2(cc.y, __float_as_int(vv.y));
    int p2 = atomicAdd(&g_woff[rr.z], 1);
    g_edges[p2] = make_int2(cc.z, __float_as_int(vv.z));
    int p3 = atomicAdd(&g_woff[rr.w], 1);
    g_edges[p3] = make_int2(cc.w, __float_as_int(vv.w));
}

// ---------------------------------------------------------------------------
// Shared per-row SpMM + fusion body.
// ---------------------------------------------------------------------------
__device__ __forceinline__ void spmm_row(int row, int c, const uint4* cur, uint4* next,
                                         const float* ulw, const float* ilw, int layer) {
    int s = __ldg(&g_rowptr[row]);
    int t = __ldg(&g_rowptr[row + 1]);

    float2 s0 = make_float2(0.f, 0.f), s1 = s0, s2 = s0, s3 = s0;

    int e = s;
    for (; e + 4 <= t; e += 4) {
        int2 e0 = __ldg(&g_edges[e + 0]);
        int2 e1 = __ldg(&g_edges[e + 1]);
        int2 e2 = __ldg(&g_edges[e + 2]);
        int2 e3 = __ldg(&g_edges[e + 3]);
        uint4 x0 = __ldg(&cur[e0.x * 8 + c]);
        uint4 x1 = __ldg(&cur[e1.x * 8 + c]);
        uint4 x2 = __ldg(&cur[e2.x * 8 + c]);
        uint4 x3 = __ldg(&cur[e3.x * 8 + c]);
        float v0 = __int_as_float(e0.y), v1 = __int_as_float(e1.y);
        float v2 = __int_as_float(e2.y), v3 = __int_as_float(e3.y);
        float2 f;
        f = __half22float2(u_to_h2(x0.x)); s0.x += v0*f.x; s0.y += v0*f.y;
        f = __half22float2(u_to_h2(x0.y)); s1.x += v0*f.x; s1.y += v0*f.y;
        f = __half22float2(u_to_h2(x0.z)); s2.x += v0*f.x; s2.y += v0*f.y;
        f = __half22float2(u_to_h2(x0.w)); s3.x += v0*f.x; s3.y += v0*f.y;
        f = __half22float2(u_to_h2(x1.x)); s0.x += v1*f.x; s0.y += v1*f.y;
        f = __half22float2(u_to_h2(x1.y)); s1.x += v1*f.x; s1.y += v1*f.y;
        f = __half22float2(u_to_h2(x1.z)); s2.x += v1*f.x; s2.y += v1*f.y;
        f = __half22float2(u_to_h2(x1.w)); s3.x += v1*f.x; s3.y += v1*f.y;
        f = __half22float2(u_to_h2(x2.x)); s0.x += v2*f.x; s0.y += v2*f.y;
        f = __half22float2(u_to_h2(x2.y)); s1.x += v2*f.x; s1.y += v2*f.y;
        f = __half22float2(u_to_h2(x2.z)); s2.x += v2*f.x; s2.y += v2*f.y;
        f = __half22float2(u_to_h2(x2.w)); s3.x += v2*f.x; s3.y += v2*f.y;
        f = __half22float2(u_to_h2(x3.x)); s0.x += v3*f.x; s0.y += v3*f.y;
        f = __half22float2(u_to_h2(x3.y)); s1.x += v3*f.x; s1.y += v3*f.y;
        f = __half22float2(u_to_h2(x3.z)); s2.x += v3*f.x; s2.y += v3*f.y;
        f = __half22float2(u_to_h2(x3.w)); s3.x += v3*f.x; s3.y += v3*f.y;
    }
    for (; e < t; e++) {
        int2 ed = __ldg(&g_edges[e]);
        uint4 x = __ldg(&cur[ed.x * 8 + c]);
        float v = __int_as_float(ed.y);
        float2 f;
        f = __half22float2(u_to_h2(x.x)); s0.x += v*f.x; s0.y += v*f.y;
        f = __half22float2(u_to_h2(x.y)); s1.x += v*f.x; s1.y += v*f.y;
        f = __half22float2(u_to_h2(x.z)); s2.x += v*f.x; s2.y += v*f.y;
        f = __half22float2(u_to_h2(x.w)); s3.x += v*f.x; s3.y += v*f.y;
    }

    bool isU = row < NU;
    float w = sigmoidf(isU ? ulw[layer] : ilw[layer]);
    float omw = 1.0f - w;
    uint4 sh16 = __ldg((const uint4*)g_side + (size_t)row * 8 + c);
    float2 d0 = __half22float2(u_to_h2(sh16.x));
    float2 d1 = __half22float2(u_to_h2(sh16.y));
    float2 d2 = __half22float2(u_to_h2(sh16.z));
    float2 d3 = __half22float2(u_to_h2(sh16.w));

    uint4 hout;
    hout.x = h2_to_u(__floats2half2_rn(w * s0.x + omw * d0.x, w * s0.y + omw * d0.y));
    hout.y = h2_to_u(__floats2half2_rn(w * s1.x + omw * d1.x, w * s1.y + omw * d1.y));
    hout.z = h2_to_u(__floats2half2_rn(w * s2.x + omw * d2.x, w * s2.y + omw * d2.y));
    hout.w = h2_to_u(__floats2half2_rn(w * s3.x + omw * d3.x, w * s3.y + omw * d3.y));
    next[row * 8 + c] = hout;
}

// Full-graph layer (layers 1..NL-1).
__global__ void k_spmm_fuse(const float* __restrict__ ulw, const float* __restrict__ ilw,
                            int layer) {
    int tid = blockIdx.x * blockDim.x + threadIdx.x;
    int row = tid >> 3;
    int c   = tid & 7;
    if (row >= NN) return;
    spmm_row(row, c, (const uint4*)g_embs[layer - 1], (uint4*)g_embs[layer],
             ulw, ilw, layer);
}

// Final layer: only the sampled rows (users + items). Duplicates write
// identical values — deterministic.
__global__ void k_spmm_fuse_last(const float* __restrict__ ulw, const float* __restrict__ ilw,
                                 const int* __restrict__ users, const int* __restrict__ items) {
    int tid = blockIdx.x * blockDim.x + threadIdx.x;
    int j = tid >> 3;
    int c = tid & 7;
    if (j >= 2 * NB) return;
    int row = (j < NB) ? __ldg(&users[j]) : (NU + __ldg(&items[j - NB]));
    spmm_row(row, c, (const uint4*)g_embs[NL - 1], (uint4*)g_embs[NL],
             ulw, ilw, NL);
}

// ---------------------------------------------------------------------------
// Final dot over on-the-fly 4-layer sum.
// ---------------------------------------------------------------------------
__global__ void k_dot(const int* __restrict__ users, const int* __restrict__ items,
                      float* __restrict__ out) {
    int w = (blockIdx.x * blockDim.x + threadIdx.x) >> 5;
    int l = threadIdx.x & 31;
    if (w >= NB) return;
    size_t uo = (size_t)users[w] * 32 + l;
    size_t io = (size_t)(NU + items[w]) * 32 + l;
    float ux = 0.f, uy = 0.f, ix = 0.f, iy = 0.f;
    #pragma unroll
    for (int L = 0; L <= NL; L++) {
        float2 fu = __half22float2(((const __half2*)g_embs[L])[uo]);
        float2 fi = __half22float2(((const __half2*)g_embs[L])[io]);
        ux += fu.x; uy += fu.y;
        ix += fi.x; iy += fi.y;
    }
    float s = ux * ix + uy * iy;
    #pragma unroll
    for (int o = 16; o > 0; o >>= 1)
        s += __shfl_down_sync(0xffffffffu, s, o);
    if (l == 0) out[w] = s * (1.0f / 16.0f);
}

extern "C" void kernel_launch(void* const* d_in, const int* in_sizes, int n_in,
                              void* d_out, int out_size) {
    const float* user_emb    = (const float*)d_in[0];
    const float* item_emb    = (const float*)d_in[1];
    const float* symptom_emb = (const float*)d_in[2];
    const float* herb_emb    = (const float*)d_in[3];
    const float* user_lw     = (const float*)d_in[4];
    const float* item_lw     = (const float*)d_in[5];
    const float* edge_val    = (const float*)d_in[6];
    const int*   edge_row    = (const int*)d_in[7];
    const int*   edge_col    = (const int*)d_in[8];
    const int*   users       = (const int*)d_in[9];
    const int*   items       = (const int*)d_in[10];
    float* out = (float*)d_out;

    static cudaStream_t s2 = nullptr;
    static cudaEvent_t ev_fork = nullptr, ev_join = nullptr;
    if (!s2) {
        cudaStreamCreateWithFlags(&s2, cudaStreamNonBlocking);
        cudaEventCreateWithFlags(&ev_fork, cudaEventDisableTiming);
        cudaEventCreateWithFlags(&ev_join, cudaEventDisableTiming);
    }

    const int n4 = NN * DD / 4;
    const int TB = 256;
    const int gElem  = (n4 + TB - 1) / TB;
    const int gEdge4 = (NE / 4 + TB - 1) / TB;
    const int gRow   = (NN * 8 + TB - 1) / TB;
    const int gLast  = (2 * NB * 8 + TB - 1) / TB;
    const int gN     = (NN + TB - 1) / TB;

    // Fork: CSR build on s2, fuse0 on the main stream (disjoint state).
    cudaEventRecord(ev_fork, 0);
    cudaStreamWaitEvent(s2, ev_fork, 0);
    k_zero_count<<<gN, TB, 0, s2>>>();
    k_count<<<gEdge4, TB, 0, s2>>>(edge_row);
    k_scan_blocks<<<SCAN_NBLK, SCAN_BS, 0, s2>>>();
    k_scan_add<<<gN, TB, 0, s2>>>();
    k_place<<<gEdge4, TB, 0, s2>>>(edge_val, edge_row, edge_col);
    cudaEventRecord(ev_join, s2);

    k_fuse0<<<gElem, TB>>>(user_emb, item_emb, symptom_emb, herb_emb, user_lw, item_lw);

    // Join: layers need both fuse0 (main stream) and CSR (s2).
    cudaStreamWaitEvent(0, ev_join, 0);

    for (int layer = 1; layer < NL; layer++) {
        k_spmm_fuse<<<gRow, TB>>>(user_lw, item_lw, layer);
    }
    k_spmm_fuse_last<<<gLast, TB>>>(user_lw, item_lw, users, items);
    k_dot<<<(NB * 32 + TB - 1) / TB, TB>>>(users, items, out);
}

// round 17
// speedup vs baseline: 1.2886x; 1.0088x over previous
#include <cuda_runtime.h>
#include <cuda_fp16.h>

#define NU 100000
#define NI 100000
#define DD 64
#define NL 3
#define NE 6400000
#define NB 16384
#define NN (NU + NI)

#define SCAN_BS 512
#define SCAN_NBLK ((NN + SCAN_BS - 1) / SCAN_BS)   // 391

// Scratch — __device__ globals, no allocation.
__device__ __half g_embs[NL + 1][(size_t)NN * DD];  // fp16 per-layer outputs
__device__ __half g_side[(size_t)NN * DD];          // fp16 concat(symptom, herb)
__device__ int    g_count[NN];
__device__ int    g_rowptr[NN + 1];
__device__ int    g_woff[NN];
__device__ int    g_bsum[SCAN_NBLK];                // per-scan-block totals (unscanned)
__device__ __align__(16) int2 g_edges[NE];          // packed {col, val-bits}

__device__ __forceinline__ float sigmoidf(float x) {
    return 1.0f / (1.0f + __expf(-x));
}
__device__ __forceinline__ unsigned int h2_to_u(__half2 h) {
    return *reinterpret_cast<unsigned int*>(&h);
}
__device__ __forceinline__ __half2 u_to_h2(unsigned int u) {
    return *reinterpret_cast<__half2*>(&u);
}

// ---------------------------------------------------------------------------
// Zero row counters (head of the CSR stream).
// ---------------------------------------------------------------------------
__global__ void k_zero_count() {
    int i = blockIdx.x * blockDim.x + threadIdx.x;
    if (i < NN) g_count[i] = 0;
}

// ---------------------------------------------------------------------------
// Layer-0 fusion + fp16 side table (runs concurrently with CSR stream).
// ---------------------------------------------------------------------------
__global__ void k_fuse0(const float* __restrict__ ue, const float* __restrict__ ie,
                        const float* __restrict__ se, const float* __restrict__ he,
                        const float* __restrict__ ulw, const float* __restrict__ ilw) {
    int idx = blockIdx.x * blockDim.x + threadIdx.x;
    const int n4 = NN * DD / 4;
    if (idx >= n4) return;
    float4 r, sd;
    if (idx < NU * DD / 4) {
        float a = sigmoidf(ulw[0]);
        float4 x = ((const float4*)ue)[idx];
        sd = ((const float4*)se)[idx];
        r.x = a * x.x + (1.0f - a) * sd.x;
        r.y = a * x.y + (1.0f - a) * sd.y;
        r.z = a * x.z + (1.0f - a) * sd.z;
        r.w = a * x.w + (1.0f - a) * sd.w;
    } else {
        int j = idx - NU * DD / 4;
        float b = sigmoidf(ilw[0]);
        float4 x = ((const float4*)ie)[j];
        sd = ((const float4*)he)[j];
        r.x = b * x.x + (1.0f - b) * sd.x;
        r.y = b * x.y + (1.0f - b) * sd.y;
        r.z = b * x.z + (1.0f - b) * sd.z;
        r.w = b * x.w + (1.0f - b) * sd.w;
    }
    uint2 hp;
    hp.x = h2_to_u(__floats2half2_rn(r.x, r.y));
    hp.y = h2_to_u(__floats2half2_rn(r.z, r.w));
    ((uint2*)g_embs[0])[idx] = hp;
    uint2 hs;
    hs.x = h2_to_u(__floats2half2_rn(sd.x, sd.y));
    hs.y = h2_to_u(__floats2half2_rn(sd.z, sd.w));
    ((uint2*)g_side)[idx] = hs;
}

// ---------------------------------------------------------------------------
// CSR build — vectorized histogram (NE % 4 == 0)
// ---------------------------------------------------------------------------
__global__ void k_count(const int* __restrict__ er) {
    int i = blockIdx.x * blockDim.x + threadIdx.x;
    if (i >= NE / 4) return;
    int4 r = __ldg(&((const int4*)er)[i]);
    atomicAdd(&g_count[r.x], 1);
    atomicAdd(&g_count[r.y], 1);
    atomicAdd(&g_count[r.z], 1);
    atomicAdd(&g_count[r.w], 1);
}

__global__ void k_scan_blocks() {
    __shared__ int sh[SCAN_BS];
    int i = blockIdx.x * SCAN_BS + threadIdx.x;
    int v = (i < NN) ? g_count[i] : 0;
    sh[threadIdx.x] = v;
    __syncthreads();
    #pragma unroll
    for (int o = 1; o < SCAN_BS; o <<= 1) {
        int t = (threadIdx.x >= o) ? sh[threadIdx.x - o] : 0;
        __syncthreads();
        sh[threadIdx.x] += t;
        __syncthreads();
    }
    if (i < NN) g_rowptr[i] = sh[threadIdx.x] - v;   // block-local exclusive
    if (threadIdx.x == SCAN_BS - 1) g_bsum[blockIdx.x] = sh[SCAN_BS - 1];
}

// Merged scan_tops + scan_add (R12-proven).
__global__ void k_scan_add() {
    __shared__ int s_off;
    int b = blockIdx.x;
    int sb = (b * 256) >> 9;              // owning scan-block index
    if (threadIdx.x < 32) {
        int acc = 0;
        for (int j = threadIdx.x; j < sb; j += 32) acc += g_bsum[j];
        #pragma unroll
        for (int o = 16; o > 0; o >>= 1)
            acc += __shfl_down_sync(0xffffffffu, acc, o);
        if (threadIdx.x == 0) s_off = acc;
    }
    __syncthreads();
    int i = b * 256 + threadIdx.x;
    if (i >= NN) return;
    int p = g_rowptr[i] + s_off;
    g_rowptr[i] = p;
    g_woff[i] = p;
    if (i == 0) g_rowptr[NN] = NE;
}

// Vectorized placement: 4 edges per thread (NE % 4 == 0).
__global__ void k_place(const float* __restrict__ ev, const int* __restrict__ er,
                        const int* __restrict__ ec) {
    int i = blockIdx.x * blockDim.x + threadIdx.x;
    if (i >= NE / 4) return;
    int4   rr = __ldg(&((const int4*)er)[i]);
    int4   cc = __ldg(&((const int4*)ec)[i]);
    float4 vv = __ldg(&((const float4*)ev)[i]);
    int p0 = atomicAdd(&g_woff[rr.x], 1);
    g_edges[p0] = make_int2(cc.x, __float_as_int(vv.x));
    int p1 = atomicAdd(&g_woff[rr.y], 1);
    g_edges[p1] = make_int2(cc.y, __float_as_int(vv.y));
    int p2 = atomicAdd(&g_woff[rr.z], 1);
    g_edges[p2] = make_int2(cc.z, __float_as_int(vv.z));
    int p3 = atomicAdd(&g_woff[rr.w], 1);
    g_edges[p3] = make_int2(cc.w, __float_as_int(vv.w));
}

// ---------------------------------------------------------------------------
// Full-graph SpMM layer (layers 1..NL-1): 8 threads/row, 8 dims each.
// ---------------------------------------------------------------------------
__global__ void k_spmm_fuse(const float* __restrict__ ulw, const float* __restrict__ ilw,
                            int layer) {
    int tid = blockIdx.x * blockDim.x + threadIdx.x;
    int row = tid >> 3;
    int c   = tid & 7;
    if (row >= NN) return;

    const uint4* cur  = (const uint4*)g_embs[layer - 1];
    uint4*       next = (uint4*)g_embs[layer];

    int s = __ldg(&g_rowptr[row]);
    int t = __ldg(&g_rowptr[row + 1]);

    float2 s0 = make_float2(0.f, 0.f), s1 = s0, s2 = s0, s3 = s0;

    int e = s;
    for (; e + 4 <= t; e += 4) {
        int2 e0 = __ldg(&g_edges[e + 0]);
        int2 e1 = __ldg(&g_edges[e + 1]);
        int2 e2 = __ldg(&g_edges[e + 2]);
        int2 e3 = __ldg(&g_edges[e + 3]);
        uint4 x0 = __ldg(&cur[e0.x * 8 + c]);
        uint4 x1 = __ldg(&cur[e1.x * 8 + c]);
        uint4 x2 = __ldg(&cur[e2.x * 8 + c]);
        uint4 x3 = __ldg(&cur[e3.x * 8 + c]);
        float v0 = __int_as_float(e0.y), v1 = __int_as_float(e1.y);
        float v2 = __int_as_float(e2.y), v3 = __int_as_float(e3.y);
        float2 f;
        f = __half22float2(u_to_h2(x0.x)); s0.x += v0*f.x; s0.y += v0*f.y;
        f = __half22float2(u_to_h2(x0.y)); s1.x += v0*f.x; s1.y += v0*f.y;
        f = __half22float2(u_to_h2(x0.z)); s2.x += v0*f.x; s2.y += v0*f.y;
        f = __half22float2(u_to_h2(x0.w)); s3.x += v0*f.x; s3.y += v0*f.y;
        f = __half22float2(u_to_h2(x1.x)); s0.x += v1*f.x; s0.y += v1*f.y;
        f = __half22float2(u_to_h2(x1.y)); s1.x += v1*f.x; s1.y += v1*f.y;
        f = __half22float2(u_to_h2(x1.z)); s2.x += v1*f.x; s2.y += v1*f.y;
        f = __half22float2(u_to_h2(x1.w)); s3.x += v1*f.x; s3.y += v1*f.y;
        f = __half22float2(u_to_h2(x2.x)); s0.x += v2*f.x; s0.y += v2*f.y;
        f = __half22float2(u_to_h2(x2.y)); s1.x += v2*f.x; s1.y += v2*f.y;
        f = __half22float2(u_to_h2(x2.z)); s2.x += v2*f.x; s2.y += v2*f.y;
        f = __half22float2(u_to_h2(x2.w)); s3.x += v2*f.x; s3.y += v2*f.y;
        f = __half22float2(u_to_h2(x3.x)); s0.x += v3*f.x; s0.y += v3*f.y;
        f = __half22float2(u_to_h2(x3.y)); s1.x += v3*f.x; s1.y += v3*f.y;
        f = __half22float2(u_to_h2(x3.z)); s2.x += v3*f.x; s2.y += v3*f.y;
        f = __half22float2(u_to_h2(x3.w)); s3.x += v3*f.x; s3.y += v3*f.y;
    }
    for (; e < t; e++) {
        int2 ed = __ldg(&g_edges[e]);
        uint4 x = __ldg(&cur[ed.x * 8 + c]);
        float v = __int_as_float(ed.y);
        float2 f;
        f = __half22float2(u_to_h2(x.x)); s0.x += v*f.x; s0.y += v*f.y;
        f = __half22float2(u_to_h2(x.y)); s1.x += v*f.x; s1.y += v*f.y;
        f = __half22float2(u_to_h2(x.z)); s2.x += v*f.x; s2.y += v*f.y;
        f = __half22float2(u_to_h2(x.w)); s3.x += v*f.x; s3.y += v*f.y;
    }

    bool isU = row < NU;
    float w = sigmoidf(isU ? ulw[layer] : ilw[layer]);
    float omw = 1.0f - w;
    uint4 sh16 = __ldg((const uint4*)g_side + (size_t)row * 8 + c);
    float2 d0 = __half22float2(u_to_h2(sh16.x));
    float2 d1 = __half22float2(u_to_h2(sh16.y));
    float2 d2 = __half22float2(u_to_h2(sh16.z));
    float2 d3 = __half22float2(u_to_h2(sh16.w));

    uint4 hout;
    hout.x = h2_to_u(__floats2half2_rn(w * s0.x + omw * d0.x, w * s0.y + omw * d0.y));
    hout.y = h2_to_u(__floats2half2_rn(w * s1.x + omw * d1.x, w * s1.y + omw * d1.y));
    hout.z = h2_to_u(__floats2half2_rn(w * s2.x + omw * d2.x, w * s2.y + omw * d2.y));
    hout.w = h2_to_u(__floats2half2_rn(w * s3.x + omw * d3.x, w * s3.y + omw * d3.y));
    next[row * 8 + c] = hout;
}

// ---------------------------------------------------------------------------
// Final layer: sampled rows only, ONE WARP PER ROW. Lane l owns dims 2l,2l+1
// (one half2 = 4B). Per edge the warp reads the full 128B row coalesced;
// the edge record load is a uniform broadcast. Duplicates write identical
// values — deterministic.
// ---------------------------------------------------------------------------
__global__ void k_spmm_fuse_last(const float* __restrict__ ulw, const float* __restrict__ ilw,
                                 const int* __restrict__ users, const int* __restrict__ items) {
    int gt = blockIdx.x * blockDim.x + threadIdx.x;
    int j = gt >> 5;
    int lane = threadIdx.x & 31;
    if (j >= 2 * NB) return;
    int row = (j < NB) ? __ldg(&users[j]) : (NU + __ldg(&items[j - NB]));

    const unsigned int* cur = (const unsigned int*)g_embs[NL - 1];

    int s = __ldg(&g_rowptr[row]);
    int t = __ldg(&g_rowptr[row + 1]);

    float2 acc = make_float2(0.f, 0.f);
    int e = s;
    for (; e + 4 <= t; e += 4) {
        int2 e0 = __ldg(&g_edges[e + 0]);
        int2 e1 = __ldg(&g_edges[e + 1]);
        int2 e2 = __ldg(&g_edges[e + 2]);
        int2 e3 = __ldg(&g_edges[e + 3]);
        unsigned int x0 = __ldg(&cur[e0.x * 32 + lane]);
        unsigned int x1 = __ldg(&cur[e1.x * 32 + lane]);
        unsigned int x2 = __ldg(&cur[e2.x * 32 + lane]);
        unsigned int x3 = __ldg(&cur[e3.x * 32 + lane]);
        float v0 = __int_as_float(e0.y), v1 = __int_as_float(e1.y);
        float v2 = __int_as_float(e2.y), v3 = __int_as_float(e3.y);
        float2 f;
        f = __half22float2(u_to_h2(x0)); acc.x += v0 * f.x; acc.y += v0 * f.y;
        f = __half22float2(u_to_h2(x1)); acc.x += v1 * f.x; acc.y += v1 * f.y;
        f = __half22float2(u_to_h2(x2)); acc.x += v2 * f.x; acc.y += v2 * f.y;
        f = __half22float2(u_to_h2(x3)); acc.x += v3 * f.x; acc.y += v3 * f.y;
    }
    for (; e < t; e++) {
        int2 ed = __ldg(&g_edges[e]);
        unsigned int x = __ldg(&cur[ed.x * 32 + lane]);
        float v = __int_as_float(ed.y);
        float2 f = __half22float2(u_to_h2(x));
        acc.x += v * f.x; acc.y += v * f.y;
    }

    bool isU = row < NU;
    float w = sigmoidf(isU ? ulw[NL] : ilw[NL]);
    float omw = 1.0f - w;
    float2 d = __half22float2(((const __half2*)g_side)[(size_t)row * 32 + lane]);
    ((unsigned int*)g_embs[NL])[(size_t)row * 32 + lane] =
        h2_to_u(__floats2half2_rn(w * acc.x + omw * d.x, w * acc.y + omw * d.y));
}

// ---------------------------------------------------------------------------
// Final dot over on-the-fly 4-layer sum.
// ---------------------------------------------------------------------------
__global__ void k_dot(const int* __restrict__ users, const int* __restrict__ items,
                      float* __restrict__ out) {
    int w = (blockIdx.x * blockDim.x + threadIdx.x) >> 5;
    int l = threadIdx.x & 31;
    if (w >= NB) return;
    size_t uo = (size_t)users[w] * 32 + l;
    size_t io = (size_t)(NU + items[w]) * 32 + l;
    float ux = 0.f, uy = 0.f, ix = 0.f, iy = 0.f;
    #pragma unroll
    for (int L = 0; L <= NL; L++) {
        float2 fu = __half22float2(((const __half2*)g_embs[L])[uo]);
        float2 fi = __half22float2(((const __half2*)g_embs[L])[io]);
        ux += fu.x; uy += fu.y;
        ix += fi.x; iy += fi.y;
    }
    float s = ux * ix + uy * iy;
    #pragma unroll
    for (int o = 16; o > 0; o >>= 1)
        s += __shfl_down_sync(0xffffffffu, s, o);
    if (l == 0) out[w] = s * (1.0f / 16.0f);
}

extern "C" void kernel_launch(void* const* d_in, const int* in_sizes, int n_in,
                              void* d_out, int out_size) {
    const float* user_emb    = (const float*)d_in[0];
    const float* item_emb    = (const float*)d_in[1];
    const float* symptom_emb = (const float*)d_in[2];
    const float* herb_emb    = (const float*)d_in[3];
    const float* user_lw     = (const float*)d_in[4];
    const float* item_lw     = (const float*)d_in[5];
    const float* edge_val    = (const float*)d_in[6];
    const int*   edge_row    = (const int*)d_in[7];
    const int*   edge_col    = (const int*)d_in[8];
    const int*   users       = (const int*)d_in[9];
    const int*   items       = (const int*)d_in[10];
    float* out = (float*)d_out;

    static cudaStream_t s2 = nullptr;
    static cudaEvent_t ev_fork = nullptr, ev_join = nullptr;
    if (!s2) {
        cudaStreamCreateWithFlags(&s2, cudaStreamNonBlocking);
        cudaEventCreateWithFlags(&ev_fork, cudaEventDisableTiming);
        cudaEventCreateWithFlags(&ev_join, cudaEventDisableTiming);
    }

    const int n4 = NN * DD / 4;
    const int TB = 256;
    const int gElem  = (n4 + TB - 1) / TB;
    const int gEdge4 = (NE / 4 + TB - 1) / TB;
    const int gRow   = (NN * 8 + TB - 1) / TB;
    const int gLast  = (2 * NB * 32 + TB - 1) / TB;
    const int gN     = (NN + TB - 1) / TB;

    // Fork: CSR build on s2, fuse0 on the main stream (disjoint state).
    cudaEventRecord(ev_fork, 0);
    cudaStreamWaitEvent(s2, ev_fork, 0);
    k_zero_count<<<gN, TB, 0, s2>>>();
    k_count<<<gEdge4, TB, 0, s2>>>(edge_row);
    k_scan_blocks<<<SCAN_NBLK, SCAN_BS, 0, s2>>>();
    k_scan_add<<<gN, TB, 0, s2>>>();
    k_place<<<gEdge4, TB, 0, s2>>>(edge_val, edge_row, edge_col);
    cudaEventRecord(ev_join, s2);

    k_fuse0<<<gElem, TB>>>(user_emb, item_emb, symptom_emb, herb_emb, user_lw, item_lw);

    // Join: layers need both fuse0 (main stream) and CSR (s2).
    cudaStreamWaitEvent(0, ev_join, 0);

    for (int layer = 1; layer < NL; layer++) {
        k_spmm_fuse<<<gRow, TB>>>(user_lw, item_lw, layer);
    }
    k_spmm_fuse_last<<<gLast, TB>>>(user_lw, item_lw, users, items);
    k_dot<<<(NB * 32 + TB - 1) / TB, TB>>>(users, items, out);
}